// round 1
// baseline (speedup 1.0000x reference)
#include <cuda_runtime.h>
#include <math.h>

#define BB 8
#define CC 512
#define PP 1024   // H*W
#define EE 8
#define DH 1024

// Scratch (allocated at module load; no runtime allocation)
__device__ float g_mean[BB][CC];
__device__ float g_scale[BB][2];
__device__ int   g_expert[BB][2];
__device__ float g_cbias[BB][CC];
__device__ float g_H[BB][2][DH][PP];   // 64 MB: scaled gelu activations

// ---------------------------------------------------------------------------
// Kernel 1: per-(b,c) spatial mean. One block per (b,c), 256 threads.
// ---------------------------------------------------------------------------
__global__ void mean_kernel(const float* __restrict__ x) {
    int bc = blockIdx.x;                       // b*512 + c
    const float4* p = (const float4*)(x + (size_t)bc * PP);
    float4 v = p[threadIdx.x];                 // 256*4 = 1024 elements
    float s = v.x + v.y + v.z + v.w;
    #pragma unroll
    for (int o = 16; o; o >>= 1) s += __shfl_down_sync(0xffffffffu, s, o);
    __shared__ float ws[8];
    if ((threadIdx.x & 31) == 0) ws[threadIdx.x >> 5] = s;
    __syncthreads();
    if (threadIdx.x == 0) {
        float t = 0.f;
        #pragma unroll
        for (int i = 0; i < 8; i++) t += ws[i];
        g_mean[bc >> 9][bc & 511] = t * (1.0f / PP);
    }
}

// ---------------------------------------------------------------------------
// Kernel 2: gate — logits, fp32 softmax, top-2 (first-index tie-break),
// per-(b,slot) scale = w * k[b], and combined b2 bias per (b,c).
// ---------------------------------------------------------------------------
__global__ void gate_kernel(const float* __restrict__ Wg, const float* __restrict__ bg,
                            const float* __restrict__ kk, const float* __restrict__ b2) {
    __shared__ float sl[BB][EE];
    int t = threadIdx.x;
    if (t < BB * EE) {
        int b = t >> 3, e = t & 7;
        float acc = bg[e];
        for (int c = 0; c < CC; c++) acc = fmaf(g_mean[b][c], Wg[c * EE + e], acc);
        sl[b][e] = acc;
    }
    __syncthreads();
    if (t < BB) {
        int b = t;
        float m = -1e30f;
        #pragma unroll
        for (int e = 0; e < EE; e++) m = fmaxf(m, sl[b][e]);
        float w[EE]; float sum = 0.f;
        #pragma unroll
        for (int e = 0; e < EE; e++) { w[e] = expf(sl[b][e] - m); sum += w[e]; }
        float inv = 1.0f / sum;
        #pragma unroll
        for (int e = 0; e < EE; e++) w[e] *= inv;
        int i0 = 0;
        #pragma unroll
        for (int e = 1; e < EE; e++) if (w[e] > w[i0]) i0 = e;
        int i1 = (i0 == 0) ? 1 : 0;
        #pragma unroll
        for (int e = 0; e < EE; e++) { if (e == i0 || e == i1) continue; if (w[e] > w[i1]) i1 = e; }
        float kb = kk[b];
        g_expert[b][0] = i0; g_expert[b][1] = i1;
        g_scale[b][0]  = w[i0] * kb; g_scale[b][1] = w[i1] * kb;
    }
    __syncthreads();   // orders global writes above within this block
    for (int i = t; i < BB * CC; i += blockDim.x) {
        int b = i >> 9, c = i & 511;
        g_cbias[b][c] = g_scale[b][0] * b2[g_expert[b][0] * CC + c]
                      + g_scale[b][1] * b2[g_expert[b][1] * CC + c];
    }
}

// ---------------------------------------------------------------------------
// Kernel 3: GEMM1 per active (b,slot):
//   H[d,p] = scale * gelu( sum_c W1[e][c][d] * X[b][c][p] + b1[e][d] )
// 128x128 tile, K-tile 8, 256 threads, 8x8 per thread (2x2 of 4x4 quadrants).
// ---------------------------------------------------------------------------
__global__ __launch_bounds__(256, 2)
void gemm1_kernel(const float* __restrict__ X, const float* __restrict__ W1,
                  const float* __restrict__ b1v) {
    __shared__ float As[8][128];
    __shared__ float Bs[8][128];
    int pair = blockIdx.y;
    int b = pair >> 1, slot = pair & 1;
    int e = g_expert[b][slot];
    float s = g_scale[b][slot];
    int td = (blockIdx.x >> 3) << 7;       // d tile base
    int tp = (blockIdx.x & 7) << 7;        // p tile base
    const float* A  = W1 + (size_t)e * CC * DH;   // [c][d], ld=DH
    const float* Bm = X  + (size_t)b * CC * PP;   // [c][p], ld=PP
    int tid = threadIdx.x;
    int lr = tid >> 5;                     // smem load row (k)
    int lc = (tid & 31) << 2;              // smem load col*4
    int ty = tid >> 4;                     // 0..15
    int tx = tid & 15;                     // 0..15

    float acc[8][8];
    #pragma unroll
    for (int i = 0; i < 8; i++)
        #pragma unroll
        for (int j = 0; j < 8; j++) acc[i][j] = 0.f;

    for (int c0 = 0; c0 < CC; c0 += 8) {
        *(float4*)&As[lr][lc] = *(const float4*)&A [(size_t)(c0 + lr) * DH + td + lc];
        *(float4*)&Bs[lr][lc] = *(const float4*)&Bm[(size_t)(c0 + lr) * PP + tp + lc];
        __syncthreads();
        #pragma unroll
        for (int kc = 0; kc < 8; kc++) {
            float4 a0 = *(const float4*)&As[kc][ty * 4];
            float4 a1 = *(const float4*)&As[kc][ty * 4 + 64];
            float4 b0 = *(const float4*)&Bs[kc][tx * 4];
            float4 b1_ = *(const float4*)&Bs[kc][tx * 4 + 64];
            float av[8] = {a0.x, a0.y, a0.z, a0.w, a1.x, a1.y, a1.z, a1.w};
            float bv[8] = {b0.x, b0.y, b0.z, b0.w, b1_.x, b1_.y, b1_.z, b1_.w};
            #pragma unroll
            for (int i = 0; i < 8; i++)
                #pragma unroll
                for (int j = 0; j < 8; j++)
                    acc[i][j] = fmaf(av[i], bv[j], acc[i][j]);
        }
        __syncthreads();
    }

    float* Hout = &g_H[b][slot][0][0];
    #pragma unroll
    for (int qi = 0; qi < 2; qi++)
        #pragma unroll
        for (int i = 0; i < 4; i++) {
            int d = td + qi * 64 + ty * 4 + i;
            float bias = b1v[e * DH + d];
            #pragma unroll
            for (int qj = 0; qj < 2; qj++) {
                float vals[4];
                #pragma unroll
                for (int j = 0; j < 4; j++) {
                    float xv = acc[qi * 4 + i][qj * 4 + j] + bias;
                    // exact GELU: 0.5*x*(1+erf(x/sqrt(2)))
                    vals[j] = s * (0.5f * xv * (1.0f + erff(xv * 0.70710678118654752f)));
                }
                int p = tp + qj * 64 + tx * 4;
                *(float4*)&Hout[(size_t)d * PP + p] =
                    make_float4(vals[0], vals[1], vals[2], vals[3]);
            }
        }
}

// ---------------------------------------------------------------------------
// Kernel 4: GEMM2 per batch, K folds BOTH slots (K = 2*Dh = 2048):
//   out[b][c][p] = X[b][c][p] + cbias[b][c]
//                + sum_slot sum_d H[b][slot][d][p] * W2[e_slot][d][c]
// (scale already folded into H; b2 folded into cbias)
// ---------------------------------------------------------------------------
__global__ __launch_bounds__(256, 2)
void gemm2_kernel(const float* __restrict__ X, const float* __restrict__ W2,
                  float* __restrict__ out) {
    __shared__ float As[8][128];
    __shared__ float Bs[8][128];
    int b = blockIdx.y;
    int tc = (blockIdx.x >> 3) << 7;       // c tile base (0..384)
    int tp = (blockIdx.x & 7) << 7;        // p tile base
    int e0 = g_expert[b][0], e1 = g_expert[b][1];
    const float* A0 = W2 + (size_t)e0 * DH * CC;   // [d][c], ld=CC
    const float* A1 = W2 + (size_t)e1 * DH * CC;
    const float* H0 = &g_H[b][0][0][0];            // [d][p], ld=PP
    const float* H1 = &g_H[b][1][0][0];
    int tid = threadIdx.x;
    int lr = tid >> 5;
    int lc = (tid & 31) << 2;
    int ty = tid >> 4;
    int tx = tid & 15;

    float acc[8][8];
    #pragma unroll
    for (int i = 0; i < 8; i++)
        #pragma unroll
        for (int j = 0; j < 8; j++) acc[i][j] = 0.f;

    for (int k0 = 0; k0 < 2 * DH; k0 += 8) {
        int sl = k0 >> 10;
        int d0 = k0 & (DH - 1);
        const float* A  = sl ? A1 : A0;
        const float* Hm = sl ? H1 : H0;
        *(float4*)&As[lr][lc] = *(const float4*)&A [(size_t)(d0 + lr) * CC + tc + lc];
        *(float4*)&Bs[lr][lc] = *(const float4*)&Hm[(size_t)(d0 + lr) * PP + tp + lc];
        __syncthreads();
        #pragma unroll
        for (int kc = 0; kc < 8; kc++) {
            float4 a0 = *(const float4*)&As[kc][ty * 4];
            float4 a1 = *(const float4*)&As[kc][ty * 4 + 64];
            float4 b0 = *(const float4*)&Bs[kc][tx * 4];
            float4 b1_ = *(const float4*)&Bs[kc][tx * 4 + 64];
            float av[8] = {a0.x, a0.y, a0.z, a0.w, a1.x, a1.y, a1.z, a1.w};
            float bv[8] = {b0.x, b0.y, b0.z, b0.w, b1_.x, b1_.y, b1_.z, b1_.w};
            #pragma unroll
            for (int i = 0; i < 8; i++)
                #pragma unroll
                for (int j = 0; j < 8; j++)
                    acc[i][j] = fmaf(av[i], bv[j], acc[i][j]);
        }
        __syncthreads();
    }

    #pragma unroll
    for (int qi = 0; qi < 2; qi++)
        #pragma unroll
        for (int i = 0; i < 4; i++) {
            int c = tc + qi * 64 + ty * 4 + i;
            float cb = g_cbias[b][c];
            #pragma unroll
            for (int qj = 0; qj < 2; qj++) {
                int p = tp + qj * 64 + tx * 4;
                size_t idx = ((size_t)(b * CC + c)) * PP + p;
                float4 xin = *(const float4*)&X[idx];
                float4 o;
                o.x = xin.x + cb + acc[qi * 4 + i][qj * 4 + 0];
                o.y = xin.y + cb + acc[qi * 4 + i][qj * 4 + 1];
                o.z = xin.z + cb + acc[qi * 4 + i][qj * 4 + 2];
                o.w = xin.w + cb + acc[qi * 4 + i][qj * 4 + 3];
                *(float4*)&out[idx] = o;
            }
        }
}

// ---------------------------------------------------------------------------
extern "C" void kernel_launch(void* const* d_in, const int* in_sizes, int n_in,
                              void* d_out, int out_size) {
    const float* inputs = (const float*)d_in[0];   // [8,512,32,32]
    const float* kk     = (const float*)d_in[1];   // [8,1,1,1]
    const float* Wg     = (const float*)d_in[2];   // [512,8]
    const float* bg     = (const float*)d_in[3];   // [8]
    const float* W1     = (const float*)d_in[4];   // [8,512,1024]
    const float* b1     = (const float*)d_in[5];   // [8,1024]
    const float* W2     = (const float*)d_in[6];   // [8,1024,512]
    const float* b2     = (const float*)d_in[7];   // [8,512]
    float* out = (float*)d_out;

    mean_kernel<<<BB * CC, 256>>>(inputs);
    gate_kernel<<<1, 512>>>(Wg, bg, kk, b2);
    gemm1_kernel<<<dim3(64, 16), 256>>>(inputs, W1, b1);
    gemm2_kernel<<<dim3(32, 8), 256>>>(inputs, W2, out);
}

// round 3
// speedup vs baseline: 2.6681x; 2.6681x over previous
#include <cuda_runtime.h>
#include <math.h>
#include <stdint.h>

#define BB 8
#define CC 512
#define PP 1024   // H*W
#define EE 8
#define DH 1024

// Scratch (module-load allocation; none at runtime)
__device__ float g_mean[BB][CC];
__device__ float g_scale[BB][2];
__device__ int   g_expert[BB][2];
__device__ float g_cbias[BB][CC];
__device__ float g_H[BB][2][DH][PP];   // 64 MB

// ---------------------------------------------------------------------------
// helpers
// ---------------------------------------------------------------------------
__device__ __forceinline__ uint32_t smem_u32(const void* p) {
    uint32_t a;
    asm("{ .reg .u64 t; cvta.to.shared.u64 t, %1; cvt.u32.u64 %0, t; }" : "=r"(a) : "l"(p));
    return a;
}
__device__ __forceinline__ uint32_t f2tf32(float x) {
    uint32_t r;
    asm("cvt.rna.tf32.f32 %0, %1;" : "=r"(r) : "f"(x));
    return r;
}
__device__ __forceinline__ void mma_tf32(float* d, const uint32_t* a, const uint32_t* b) {
    asm volatile(
        "mma.sync.aligned.m16n8k8.row.col.f32.tf32.tf32.f32 "
        "{%0,%1,%2,%3}, {%4,%5,%6,%7}, {%8,%9}, {%0,%1,%2,%3};"
        : "+f"(d[0]), "+f"(d[1]), "+f"(d[2]), "+f"(d[3])
        : "r"(a[0]), "r"(a[1]), "r"(a[2]), "r"(a[3]), "r"(b[0]), "r"(b[1]));
}
#define CP_ASYNC(dst, src) \
    asm volatile("cp.async.cg.shared.global [%0], [%1], 16;" :: "r"(dst), "l"(src))
#define CP_COMMIT() asm volatile("cp.async.commit_group;" ::: "memory")
#define CP_WAIT1()  asm volatile("cp.async.wait_group 1;" ::: "memory")

// XOR-swizzled smem word index for a [16][128] fp32 tile
__device__ __forceinline__ int swadr(int k, int m) {
    return k * 128 + (m ^ ((k & 3) << 3));
}

// Issue cp.async for one 16(K) x 128(MN) fp32 tile. src row stride = ldg floats.
__device__ __forceinline__ void cp_tile(uint32_t dstA, uint32_t dstB,
                                        const float* __restrict__ srcA, int ldA,
                                        const float* __restrict__ srcB, int ldB,
                                        int tid) {
#pragma unroll
    for (int i = 0; i < 2; i++) {
        int chunk = tid + (i << 8);            // 0..511
        int k = chunk >> 5;                    // 0..15
        int m4 = (chunk & 31) << 2;            // 0..124
        uint32_t off = (uint32_t)swadr(k, m4) << 2;
        CP_ASYNC(dstA + off, srcA + (size_t)k * ldA + m4);
        CP_ASYNC(dstB + off, srcB + (size_t)k * ldB + m4);
    }
}

// ---------------------------------------------------------------------------
// Kernel 1: per-(b,c) spatial mean
// ---------------------------------------------------------------------------
__global__ void mean_kernel(const float* __restrict__ x) {
    int bc = blockIdx.x;
    const float4* p = (const float4*)(x + (size_t)bc * PP);
    float4 v = p[threadIdx.x];
    float s = v.x + v.y + v.z + v.w;
#pragma unroll
    for (int o = 16; o; o >>= 1) s += __shfl_down_sync(0xffffffffu, s, o);
    __shared__ float ws[8];
    if ((threadIdx.x & 31) == 0) ws[threadIdx.x >> 5] = s;
    __syncthreads();
    if (threadIdx.x == 0) {
        float t = 0.f;
#pragma unroll
        for (int i = 0; i < 8; i++) t += ws[i];
        g_mean[bc >> 9][bc & 511] = t * (1.0f / PP);
    }
}

// ---------------------------------------------------------------------------
// Kernel 2: gate
// ---------------------------------------------------------------------------
__global__ void gate_kernel(const float* __restrict__ Wg, const float* __restrict__ bg,
                            const float* __restrict__ kk, const float* __restrict__ b2) {
    __shared__ float sl[BB][EE];
    int t = threadIdx.x;
    if (t < BB * EE) {
        int b = t >> 3, e = t & 7;
        float acc = bg[e];
        for (int c = 0; c < CC; c++) acc = fmaf(g_mean[b][c], Wg[c * EE + e], acc);
        sl[b][e] = acc;
    }
    __syncthreads();
    if (t < BB) {
        int b = t;
        float m = -1e30f;
#pragma unroll
        for (int e = 0; e < EE; e++) m = fmaxf(m, sl[b][e]);
        float w[EE]; float sum = 0.f;
#pragma unroll
        for (int e = 0; e < EE; e++) { w[e] = expf(sl[b][e] - m); sum += w[e]; }
        float inv = 1.0f / sum;
#pragma unroll
        for (int e = 0; e < EE; e++) w[e] *= inv;
        int i0 = 0;
#pragma unroll
        for (int e = 1; e < EE; e++) if (w[e] > w[i0]) i0 = e;
        int i1 = (i0 == 0) ? 1 : 0;
#pragma unroll
        for (int e = 0; e < EE; e++) { if (e == i0 || e == i1) continue; if (w[e] > w[i1]) i1 = e; }
        float kb = kk[b];
        g_expert[b][0] = i0; g_expert[b][1] = i1;
        g_scale[b][0]  = w[i0] * kb; g_scale[b][1] = w[i1] * kb;
    }
    __syncthreads();
    for (int i = t; i < BB * CC; i += blockDim.x) {
        int b = i >> 9, c = i & 511;
        g_cbias[b][c] = g_scale[b][0] * b2[g_expert[b][0] * CC + c]
                      + g_scale[b][1] * b2[g_expert[b][1] * CC + c];
    }
}

// ---------------------------------------------------------------------------
// Shared GEMM core: 128x128 tile, 8 warps (2m x 4n), warp = 64x32,
// m16n8k8 tf32 mma, K-tile 16, 3-stage cp.async pipeline.
// acc[mt][nt][4]
// ---------------------------------------------------------------------------
struct Frag { float acc[4][4][4]; };

__device__ __forceinline__ void gemm_compute_tile(const float* __restrict__ As,
                                                  const float* __restrict__ Bs,
                                                  int warp_m, int warp_n, int lane,
                                                  float acc[4][4][4]) {
#pragma unroll
    for (int ks = 0; ks < 2; ks++) {
        const int k0 = ks * 8 + (lane & 3);
        uint32_t a[4][4], bf[4][2];
#pragma unroll
        for (int mt = 0; mt < 4; mt++) {
            int m = warp_m * 64 + mt * 16 + (lane >> 2);
            a[mt][0] = f2tf32(As[swadr(k0, m)]);
            a[mt][1] = f2tf32(As[swadr(k0, m + 8)]);
            a[mt][2] = f2tf32(As[swadr(k0 + 4, m)]);
            a[mt][3] = f2tf32(As[swadr(k0 + 4, m + 8)]);
        }
#pragma unroll
        for (int nt = 0; nt < 4; nt++) {
            int n = warp_n * 32 + nt * 8 + (lane >> 2);
            bf[nt][0] = f2tf32(Bs[swadr(k0, n)]);
            bf[nt][1] = f2tf32(Bs[swadr(k0 + 4, n)]);
        }
#pragma unroll
        for (int mt = 0; mt < 4; mt++)
#pragma unroll
            for (int nt = 0; nt < 4; nt++)
                mma_tf32(acc[mt][nt], a[mt], bf[nt]);
    }
}

// ---------------------------------------------------------------------------
// Kernel 3: GEMM1  H[d,p] = s * gelu(sum_c W1[e][c][d] X[b][c][p] + b1[e][d])
// ---------------------------------------------------------------------------
__global__ __launch_bounds__(256, 2)
void gemm1_mma(const float* __restrict__ X, const float* __restrict__ W1,
               const float* __restrict__ b1v) {
    __shared__ float smA[3][16 * 128];
    __shared__ float smB[3][16 * 128];

    const int tid = threadIdx.x;
    const int wid = tid >> 5, lane = tid & 31;
    const int warp_m = wid >> 2, warp_n = wid & 3;

    const int pair = blockIdx.y;
    const int b = pair >> 1, slot = pair & 1;
    const int e = g_expert[b][slot];
    const float s = g_scale[b][slot];
    const int td = (blockIdx.x >> 3) << 7;
    const int tp = (blockIdx.x & 7) << 7;

    const float* Abase = W1 + (size_t)e * CC * DH + td;  // rows c (ld DH), cols d
    const float* Bbase = X + (size_t)b * CC * PP + tp;   // rows c (ld PP), cols p

    uint32_t sa[3], sbuf[3];
#pragma unroll
    for (int i = 0; i < 3; i++) { sa[i] = smem_u32(smA[i]); sbuf[i] = smem_u32(smB[i]); }

    const int KT = CC / 16;   // 32
    // prologue: tiles 0,1
    cp_tile(sa[0], sbuf[0], Abase, DH, Bbase, PP, tid); CP_COMMIT();
    cp_tile(sa[1], sbuf[1], Abase + (size_t)16 * DH, DH, Bbase + (size_t)16 * PP, PP, tid); CP_COMMIT();

    float acc[4][4][4];
#pragma unroll
    for (int i = 0; i < 4; i++)
#pragma unroll
        for (int j = 0; j < 4; j++)
#pragma unroll
            for (int q = 0; q < 4; q++) acc[i][j][q] = 0.f;

#pragma unroll 1
    for (int kt = 0; kt < KT; kt++) {
        CP_WAIT1();
        __syncthreads();
        if (kt + 2 < KT) {
            int st = (kt + 2) % 3;
            cp_tile(sa[st], sbuf[st],
                    Abase + (size_t)((kt + 2) * 16) * DH, DH,
                    Bbase + (size_t)((kt + 2) * 16) * PP, PP, tid);
        }
        CP_COMMIT();
        int st = kt % 3;
        gemm_compute_tile(smA[st], smB[st], warp_m, warp_n, lane, acc);
        __syncthreads();
    }

    // epilogue: bias + exact gelu + scale -> g_H
    const int mrow = lane >> 2;
    const int ncol = (lane & 3) << 1;
    float* Hbase = &g_H[b][slot][0][0];
#pragma unroll
    for (int mt = 0; mt < 4; mt++) {
#pragma unroll
        for (int h = 0; h < 2; h++) {
            int d = td + warp_m * 64 + mt * 16 + mrow + h * 8;
            float bias = b1v[e * DH + d];
            float* Hrow = Hbase + (size_t)d * PP + tp + warp_n * 32;
#pragma unroll
            for (int nt = 0; nt < 4; nt++) {
                float x0 = acc[mt][nt][h * 2 + 0] + bias;
                float x1 = acc[mt][nt][h * 2 + 1] + bias;
                float2 o;
                o.x = s * (0.5f * x0 * (1.0f + erff(x0 * 0.70710678118654752f)));
                o.y = s * (0.5f * x1 * (1.0f + erff(x1 * 0.70710678118654752f)));
                *(float2*)(Hrow + nt * 8 + ncol) = o;
            }
        }
    }
}

// ---------------------------------------------------------------------------
// Kernel 4: GEMM2  out = X + cbias + sum_slot W2[e]^T H   (K = 2048)
// ---------------------------------------------------------------------------
__global__ __launch_bounds__(256, 2)
void gemm2_mma(const float* __restrict__ X, const float* __restrict__ W2,
               float* __restrict__ out) {
    __shared__ float smA[3][16 * 128];
    __shared__ float smB[3][16 * 128];

    const int tid = threadIdx.x;
    const int wid = tid >> 5, lane = tid & 31;
    const int warp_m = wid >> 2, warp_n = wid & 3;

    const int b = blockIdx.y;
    const int tc = (blockIdx.x >> 3) << 7;
    const int tp = (blockIdx.x & 7) << 7;
    const int e0 = g_expert[b][0], e1 = g_expert[b][1];

    const float* A0 = W2 + (size_t)e0 * DH * CC + tc;   // rows d (ld CC), cols c
    const float* A1 = W2 + (size_t)e1 * DH * CC + tc;
    const float* H0 = &g_H[b][0][0][tp];                // rows d (ld PP), cols p
    const float* H1 = &g_H[b][1][0][tp];

    uint32_t sa[3], sbuf[3];
#pragma unroll
    for (int i = 0; i < 3; i++) { sa[i] = smem_u32(smA[i]); sbuf[i] = smem_u32(smB[i]); }

    const int KT = 2 * DH / 16;   // 128
#define SRC_A(kt) (((kt) >> 6) ? A1 : A0) + (size_t)(((kt) & 63) * 16) * CC
#define SRC_B(kt) (((kt) >> 6) ? H1 : H0) + (size_t)(((kt) & 63) * 16) * PP

    cp_tile(sa[0], sbuf[0], SRC_A(0), CC, SRC_B(0), PP, tid); CP_COMMIT();
    cp_tile(sa[1], sbuf[1], SRC_A(1), CC, SRC_B(1), PP, tid); CP_COMMIT();

    float acc[4][4][4];
#pragma unroll
    for (int i = 0; i < 4; i++)
#pragma unroll
        for (int j = 0; j < 4; j++)
#pragma unroll
            for (int q = 0; q < 4; q++) acc[i][j][q] = 0.f;

#pragma unroll 1
    for (int kt = 0; kt < KT; kt++) {
        CP_WAIT1();
        __syncthreads();
        if (kt + 2 < KT) {
            int st = (kt + 2) % 3;
            cp_tile(sa[st], sbuf[st], SRC_A(kt + 2), CC, SRC_B(kt + 2), PP, tid);
        }
        CP_COMMIT();
        int st = kt % 3;
        gemm_compute_tile(smA[st], smB[st], warp_m, warp_n, lane, acc);
        __syncthreads();
    }
#undef SRC_A
#undef SRC_B

    // epilogue: residual + combined bias
    const int mrow = lane >> 2;
    const int ncol = (lane & 3) << 1;
#pragma unroll
    for (int mt = 0; mt < 4; mt++) {
#pragma unroll
        for (int h = 0; h < 2; h++) {
            int c = tc + warp_m * 64 + mt * 16 + mrow + h * 8;
            float cb = g_cbias[b][c];
            size_t rowbase = ((size_t)(b * CC + c)) * PP + tp + warp_n * 32;
#pragma unroll
            for (int nt = 0; nt < 4; nt++) {
                float2 xin = *(const float2*)(X + rowbase + nt * 8 + ncol);
                float2 o;
                o.x = xin.x + cb + acc[mt][nt][h * 2 + 0];
                o.y = xin.y + cb + acc[mt][nt][h * 2 + 1];
                *(float2*)(out + rowbase + nt * 8 + ncol) = o;
            }
        }
    }
}

// ---------------------------------------------------------------------------
extern "C" void kernel_launch(void* const* d_in, const int* in_sizes, int n_in,
                              void* d_out, int out_size) {
    const float* inputs = (const float*)d_in[0];
    const float* kk     = (const float*)d_in[1];
    const float* Wg     = (const float*)d_in[2];
    const float* bg     = (const float*)d_in[3];
    const float* W1     = (const float*)d_in[4];
    const float* b1     = (const float*)d_in[5];
    const float* W2     = (const float*)d_in[6];
    const float* b2     = (const float*)d_in[7];
    float* out = (float*)d_out;

    mean_kernel<<<BB * CC, 256>>>(inputs);
    gate_kernel<<<1, 512>>>(Wg, bg, kk, b2);
    gemm1_mma<<<dim3(64, 16), 256>>>(inputs, W1, b1);
    gemm2_mma<<<dim3(32, 8), 256>>>(inputs, W2, out);
}

// round 4
// speedup vs baseline: 4.9213x; 1.8444x over previous
#include <cuda_runtime.h>
#include <cuda_bf16.h>
#include <math.h>
#include <stdint.h>

#define BB 8
#define CC 512
#define PP 1024   // H*W
#define EE 8
#define DH 1024

// Scratch (module-load allocation; none at runtime)
__device__ float g_mean[BB][CC];
__device__ float g_scale[BB][2];
__device__ int   g_expert[BB][2];
__device__ float g_cbias[BB][CC];
__device__ __nv_bfloat16 g_Xbf[BB][CC][PP];        // 8 MB
__device__ __nv_bfloat16 g_W1bf[EE][CC][DH];       // 8 MB
__device__ __nv_bfloat16 g_W2bf[EE][DH][CC];       // 8 MB
__device__ __nv_bfloat16 g_Hbf[BB][2][DH][PP];     // 32 MB

// ---------------------------------------------------------------------------
// helpers
// ---------------------------------------------------------------------------
__device__ __forceinline__ uint32_t smem_u32(const void* p) {
    uint32_t a;
    asm("{ .reg .u64 t; cvta.to.shared.u64 t, %1; cvt.u32.u64 %0, t; }" : "=r"(a) : "l"(p));
    return a;
}
__device__ __forceinline__ void mma_bf16(float* d, const uint32_t* a, const uint32_t* b) {
    asm volatile(
        "mma.sync.aligned.m16n8k16.row.col.f32.bf16.bf16.f32 "
        "{%0,%1,%2,%3}, {%4,%5,%6,%7}, {%8,%9}, {%0,%1,%2,%3};"
        : "+f"(d[0]), "+f"(d[1]), "+f"(d[2]), "+f"(d[3])
        : "r"(a[0]), "r"(a[1]), "r"(a[2]), "r"(a[3]), "r"(b[0]), "r"(b[1]));
}
#define LDSM_X4_T(r0, r1, r2, r3, addr) \
    asm volatile("ldmatrix.sync.aligned.m8n8.x4.trans.shared.b16 {%0,%1,%2,%3}, [%4];" \
        : "=r"(r0), "=r"(r1), "=r"(r2), "=r"(r3) : "r"(addr))
#define CP_ASYNC(dst, src) \
    asm volatile("cp.async.cg.shared.global [%0], [%1], 16;" :: "r"(dst), "l"(src))
#define CP_COMMIT() asm volatile("cp.async.commit_group;" ::: "memory")
#define CP_WAIT1()  asm volatile("cp.async.wait_group 1;" ::: "memory")

// bf16 tile [16 k][128 mn]: row = 256B = 16 chunks of 16B; chunk' = chunk ^ (k&7)
// conflict-free for cp.async writes and ldmatrix reads.
__device__ __forceinline__ void cp_tile_bf(uint32_t dstA, uint32_t dstB,
                                           const __nv_bfloat16* __restrict__ srcA, int ldA,
                                           const __nv_bfloat16* __restrict__ srcB, int ldB,
                                           int tid) {
    int k = tid >> 4;          // 0..15
    int j = tid & 15;          // chunk 0..15
    uint32_t off = (uint32_t)((k << 8) + ((j ^ (k & 7)) << 4));
    CP_ASYNC(dstA + off, srcA + (size_t)k * ldA + j * 8);
    CP_ASYNC(dstB + off, srcB + (size_t)k * ldB + j * 8);
}

// ---------------------------------------------------------------------------
// Kernel 0: f32 -> bf16 (vectorized)
// ---------------------------------------------------------------------------
__global__ void f2bf_kernel(const float4* __restrict__ in, uint2* __restrict__ out, int n4) {
    int i = blockIdx.x * blockDim.x + threadIdx.x;
    if (i < n4) {
        float4 v = in[i];
        __nv_bfloat162 lo = __floats2bfloat162_rn(v.x, v.y);
        __nv_bfloat162 hi = __floats2bfloat162_rn(v.z, v.w);
        out[i] = make_uint2(*(uint32_t*)&lo, *(uint32_t*)&hi);
    }
}

// ---------------------------------------------------------------------------
// Kernel 1: per-(b,c) spatial mean + X -> bf16 conversion (same read)
// ---------------------------------------------------------------------------
__global__ void mean_kernel(const float* __restrict__ x) {
    int bc = blockIdx.x;
    const float4* p = (const float4*)(x + (size_t)bc * PP);
    float4 v = p[threadIdx.x];
    // emit bf16 copy
    __nv_bfloat162 lo = __floats2bfloat162_rn(v.x, v.y);
    __nv_bfloat162 hi = __floats2bfloat162_rn(v.z, v.w);
    uint2* xb = (uint2*)(&g_Xbf[0][0][0] + (size_t)bc * PP);
    xb[threadIdx.x] = make_uint2(*(uint32_t*)&lo, *(uint32_t*)&hi);

    float s = v.x + v.y + v.z + v.w;
#pragma unroll
    for (int o = 16; o; o >>= 1) s += __shfl_down_sync(0xffffffffu, s, o);
    __shared__ float ws[8];
    if ((threadIdx.x & 31) == 0) ws[threadIdx.x >> 5] = s;
    __syncthreads();
    if (threadIdx.x == 0) {
        float t = 0.f;
#pragma unroll
        for (int i = 0; i < 8; i++) t += ws[i];
        g_mean[bc >> 9][bc & 511] = t * (1.0f / PP);
    }
}

// ---------------------------------------------------------------------------
// Kernel 2: gate — warp per (b,e) logit, fp32 softmax, top-2, cbias
// ---------------------------------------------------------------------------
__global__ void gate_kernel(const float* __restrict__ Wg, const float* __restrict__ bg,
                            const float* __restrict__ kk, const float* __restrict__ b2) {
    __shared__ float sl[BB][EE];
    int t = threadIdx.x;
    int w = t >> 5, lane = t & 31;
    // 16 warps: warp w covers 4 (b,e) pairs: pair = w*4..w*4+3
#pragma unroll
    for (int q = 0; q < 4; q++) {
        int pe = w * 4 + q;            // 0..63
        int b = pe >> 3, e = pe & 7;
        float acc = 0.f;
        for (int c = lane; c < CC; c += 32)
            acc = fmaf(g_mean[b][c], Wg[c * EE + e], acc);
#pragma unroll
        for (int o = 16; o; o >>= 1) acc += __shfl_down_sync(0xffffffffu, acc, o);
        if (lane == 0) sl[b][e] = acc + bg[e];
    }
    __syncthreads();
    if (t < BB) {
        int b = t;
        float m = -1e30f;
#pragma unroll
        for (int e = 0; e < EE; e++) m = fmaxf(m, sl[b][e]);
        float wv[EE]; float sum = 0.f;
#pragma unroll
        for (int e = 0; e < EE; e++) { wv[e] = expf(sl[b][e] - m); sum += wv[e]; }
        float inv = 1.0f / sum;
#pragma unroll
        for (int e = 0; e < EE; e++) wv[e] *= inv;
        int i0 = 0;
#pragma unroll
        for (int e = 1; e < EE; e++) if (wv[e] > wv[i0]) i0 = e;
        int i1 = (i0 == 0) ? 1 : 0;
#pragma unroll
        for (int e = 0; e < EE; e++) { if (e == i0 || e == i1) continue; if (wv[e] > wv[i1]) i1 = e; }
        float kb = kk[b];
        g_expert[b][0] = i0; g_expert[b][1] = i1;
        g_scale[b][0]  = wv[i0] * kb; g_scale[b][1] = wv[i1] * kb;
    }
    __syncthreads();
    for (int i = t; i < BB * CC; i += blockDim.x) {
        int b = i >> 9, c = i & 511;
        g_cbias[b][c] = g_scale[b][0] * b2[g_expert[b][0] * CC + c]
                      + g_scale[b][1] * b2[g_expert[b][1] * CC + c];
    }
}

// ---------------------------------------------------------------------------
// GEMM core: 128x128 CTA tile, 8 warps (2m x 4n), warp 64x32, bf16 m16n8k16,
// K-tile 16, ldmatrix.x4.trans fragments, 3-stage cp.async pipeline.
// ---------------------------------------------------------------------------
__device__ __forceinline__ void compute_tile_bf(uint32_t sA, uint32_t sB,
                                                int warp_m, int warp_n, int lane,
                                                float acc[4][4][4]) {
    // A fragments: lane -> (k, m-half)
    int kA = (lane & 7) | ((lane & 16) >> 1);    // +8 for lanes 16-31
    int mh = (lane & 8) >> 3;                    // m +8 for lanes 8-15
    uint32_t a[4][4];
#pragma unroll
    for (int mt = 0; mt < 4; mt++) {
        int chunk = ((warp_m * 64 + mt * 16) >> 3) + mh;
        uint32_t addr = sA + (uint32_t)((kA << 8) + (((chunk) ^ (kA & 7)) << 4));
        LDSM_X4_T(a[mt][0], a[mt][1], a[mt][2], a[mt][3], addr);
    }
    // B fragments: lane -> (k, n-half)
    int kB = (lane & 7) | (lane & 8);            // +8 for lanes 8-15
    int nh = (lane & 16) >> 1;                   // n +8 for lanes 16-31
    uint32_t bfr[2][4];
#pragma unroll
    for (int ntp = 0; ntp < 2; ntp++) {
        int chunk = (warp_n * 32 + ntp * 16 + nh) >> 3;
        uint32_t addr = sB + (uint32_t)((kB << 8) + ((chunk ^ (kB & 7)) << 4));
        LDSM_X4_T(bfr[ntp][0], bfr[ntp][1], bfr[ntp][2], bfr[ntp][3], addr);
    }
#pragma unroll
    for (int mt = 0; mt < 4; mt++)
#pragma unroll
        for (int nt = 0; nt < 4; nt++)
            mma_bf16(acc[mt][nt], a[mt], &bfr[nt >> 1][(nt & 1) << 1]);
}

// ---------------------------------------------------------------------------
// Kernel 3: GEMM1  H[d,p] = s * gelu(sum_c W1[e][c][d] X[b][c][p] + b1[e][d])
// ---------------------------------------------------------------------------
__global__ __launch_bounds__(256, 2)
void gemm1_mma(const float* __restrict__ b1v) {
    __shared__ __align__(256) char smA[3][4096];
    __shared__ __align__(256) char smB[3][4096];

    const int tid = threadIdx.x;
    const int wid = tid >> 5, lane = tid & 31;
    const int warp_m = wid >> 2, warp_n = wid & 3;

    const int pair = blockIdx.y;
    const int b = pair >> 1, slot = pair & 1;
    const int e = g_expert[b][slot];
    const float s = g_scale[b][slot];
    const int td = (blockIdx.x >> 3) << 7;
    const int tp = (blockIdx.x & 7) << 7;

    const __nv_bfloat16* Abase = &g_W1bf[e][0][0] + td;   // rows c (ld DH), cols d
    const __nv_bfloat16* Bbase = &g_Xbf[b][0][0] + tp;    // rows c (ld PP), cols p

    uint32_t sa[3], sb[3];
#pragma unroll
    for (int i = 0; i < 3; i++) { sa[i] = smem_u32(smA[i]); sb[i] = smem_u32(smB[i]); }

    const int KT = CC / 16;   // 32
    cp_tile_bf(sa[0], sb[0], Abase, DH, Bbase, PP, tid); CP_COMMIT();
    cp_tile_bf(sa[1], sb[1], Abase + (size_t)16 * DH, DH, Bbase + (size_t)16 * PP, PP, tid); CP_COMMIT();

    float acc[4][4][4];
#pragma unroll
    for (int i = 0; i < 4; i++)
#pragma unroll
        for (int j = 0; j < 4; j++)
#pragma unroll
            for (int q = 0; q < 4; q++) acc[i][j][q] = 0.f;

#pragma unroll 1
    for (int kt = 0; kt < KT; kt++) {
        CP_WAIT1();
        __syncthreads();
        if (kt + 2 < KT) {
            int st = (kt + 2) % 3;
            cp_tile_bf(sa[st], sb[st],
                       Abase + (size_t)((kt + 2) * 16) * DH, DH,
                       Bbase + (size_t)((kt + 2) * 16) * PP, PP, tid);
        }
        CP_COMMIT();
        int st = kt % 3;
        compute_tile_bf(sa[st], sb[st], warp_m, warp_n, lane, acc);
        __syncthreads();
    }

    // epilogue: bias + exact gelu + scale -> g_Hbf (bf16)
    const int mrow = lane >> 2;
    const int ncol = (lane & 3) << 1;
    __nv_bfloat16* Hbase = &g_Hbf[b][slot][0][0];
#pragma unroll
    for (int mt = 0; mt < 4; mt++) {
#pragma unroll
        for (int h = 0; h < 2; h++) {
            int d = td + warp_m * 64 + mt * 16 + mrow + h * 8;
            float bias = b1v[e * DH + d];
            __nv_bfloat16* Hrow = Hbase + (size_t)d * PP + tp + warp_n * 32;
#pragma unroll
            for (int nt = 0; nt < 4; nt++) {
                float x0 = acc[mt][nt][h * 2 + 0] + bias;
                float x1 = acc[mt][nt][h * 2 + 1] + bias;
                float o0 = s * (0.5f * x0 * (1.0f + erff(x0 * 0.70710678118654752f)));
                float o1 = s * (0.5f * x1 * (1.0f + erff(x1 * 0.70710678118654752f)));
                __nv_bfloat162 pk = __floats2bfloat162_rn(o0, o1);
                *(uint32_t*)(Hrow + nt * 8 + ncol) = *(uint32_t*)&pk;
            }
        }
    }
}

// ---------------------------------------------------------------------------
// Kernel 4: GEMM2  out = X + cbias + sum_slot W2[e]^T H   (K = 2048)
// ---------------------------------------------------------------------------
__global__ __launch_bounds__(256, 2)
void gemm2_mma(const float* __restrict__ X, float* __restrict__ out) {
    __shared__ __align__(256) char smA[3][4096];
    __shared__ __align__(256) char smB[3][4096];

    const int tid = threadIdx.x;
    const int wid = tid >> 5, lane = tid & 31;
    const int warp_m = wid >> 2, warp_n = wid & 3;

    const int b = blockIdx.y;
    const int tc = (blockIdx.x >> 3) << 7;
    const int tp = (blockIdx.x & 7) << 7;
    const int e0 = g_expert[b][0], e1 = g_expert[b][1];

    const __nv_bfloat16* A0 = &g_W2bf[e0][0][0] + tc;   // rows d (ld CC), cols c
    const __nv_bfloat16* A1 = &g_W2bf[e1][0][0] + tc;
    const __nv_bfloat16* H0 = &g_Hbf[b][0][0][0] + tp;  // rows d (ld PP), cols p
    const __nv_bfloat16* H1 = &g_Hbf[b][1][0][0] + tp;

    uint32_t sa[3], sb[3];
#pragma unroll
    for (int i = 0; i < 3; i++) { sa[i] = smem_u32(smA[i]); sb[i] = smem_u32(smB[i]); }

    const int KT = 2 * DH / 16;   // 128
#define SRC_A(kt) ((((kt) >> 6) ? A1 : A0) + (size_t)(((kt) & 63) * 16) * CC)
#define SRC_B(kt) ((((kt) >> 6) ? H1 : H0) + (size_t)(((kt) & 63) * 16) * PP)

    cp_tile_bf(sa[0], sb[0], SRC_A(0), CC, SRC_B(0), PP, tid); CP_COMMIT();
    cp_tile_bf(sa[1], sb[1], SRC_A(1), CC, SRC_B(1), PP, tid); CP_COMMIT();

    float acc[4][4][4];
#pragma unroll
    for (int i = 0; i < 4; i++)
#pragma unroll
        for (int j = 0; j < 4; j++)
#pragma unroll
            for (int q = 0; q < 4; q++) acc[i][j][q] = 0.f;

#pragma unroll 1
    for (int kt = 0; kt < KT; kt++) {
        CP_WAIT1();
        __syncthreads();
        if (kt + 2 < KT) {
            int st = (kt + 2) % 3;
            cp_tile_bf(sa[st], sb[st], SRC_A(kt + 2), CC, SRC_B(kt + 2), PP, tid);
        }
        CP_COMMIT();
        int st = kt % 3;
        compute_tile_bf(sa[st], sb[st], warp_m, warp_n, lane, acc);
        __syncthreads();
    }
#undef SRC_A
#undef SRC_B

    // epilogue: residual (fp32) + combined bias
    const int mrow = lane >> 2;
    const int ncol = (lane & 3) << 1;
#pragma unroll
    for (int mt = 0; mt < 4; mt++) {
#pragma unroll
        for (int h = 0; h < 2; h++) {
            int c = tc + warp_m * 64 + mt * 16 + mrow + h * 8;
            float cb = g_cbias[b][c];
            size_t rowbase = ((size_t)(b * CC + c)) * PP + tp + warp_n * 32;
#pragma unroll
            for (int nt = 0; nt < 4; nt++) {
                float2 xin = *(const float2*)(X + rowbase + nt * 8 + ncol);
                float2 o;
                o.x = xin.x + cb + acc[mt][nt][h * 2 + 0];
                o.y = xin.y + cb + acc[mt][nt][h * 2 + 1];
                *(float2*)(out + rowbase + nt * 8 + ncol) = o;
            }
        }
    }
}

// ---------------------------------------------------------------------------
extern "C" void kernel_launch(void* const* d_in, const int* in_sizes, int n_in,
                              void* d_out, int out_size) {
    const float* inputs = (const float*)d_in[0];
    const float* kk     = (const float*)d_in[1];
    const float* Wg     = (const float*)d_in[2];
    const float* bg     = (const float*)d_in[3];
    const float* W1     = (const float*)d_in[4];
    const float* b1     = (const float*)d_in[5];
    const float* W2     = (const float*)d_in[6];
    const float* b2     = (const float*)d_in[7];
    float* out = (float*)d_out;

    __nv_bfloat16 *w1bf_p, *w2bf_p;
    cudaGetSymbolAddress((void**)&w1bf_p, g_W1bf);
    cudaGetSymbolAddress((void**)&w2bf_p, g_W2bf);

    const int n4 = EE * CC * DH / 4;   // 1M float4 per weight tensor
    f2bf_kernel<<<(n4 + 255) / 256, 256>>>((const float4*)W1, (uint2*)w1bf_p, n4);
    f2bf_kernel<<<(n4 + 255) / 256, 256>>>((const float4*)W2, (uint2*)w2bf_p, n4);
    mean_kernel<<<BB * CC, 256>>>(inputs);
    gate_kernel<<<1, 512>>>(Wg, bg, kk, b2);
    gemm1_mma<<<dim3(64, 16), 256>>>(b1);
    gemm2_mma<<<dim3(32, 8), 256>>>(inputs, out);
}

// round 5
// speedup vs baseline: 5.4843x; 1.1144x over previous
#include <cuda_runtime.h>
#include <cuda_bf16.h>
#include <math.h>
#include <stdint.h>

#define BB 8
#define CC 512
#define PP 1024   // H*W
#define EE 8
#define DH 1024

// Scratch (module-load allocation; none at runtime)
__device__ float g_mean[BB][CC];
__device__ float g_scale[BB][2];
__device__ int   g_expert[BB][2];
__device__ __nv_bfloat16 g_Xbf[BB][CC][PP];        // 8 MB
__device__ __nv_bfloat16 g_W1bf[EE][CC][DH];       // 8 MB
__device__ __nv_bfloat16 g_W2bf[EE][DH][CC];       // 8 MB
__device__ __nv_bfloat16 g_Hbf[BB][2][DH][PP];     // 32 MB

// ---------------------------------------------------------------------------
// helpers
// ---------------------------------------------------------------------------
__device__ __forceinline__ uint32_t smem_u32(const void* p) {
    uint32_t a;
    asm("{ .reg .u64 t; cvta.to.shared.u64 t, %1; cvt.u32.u64 %0, t; }" : "=r"(a) : "l"(p));
    return a;
}
__device__ __forceinline__ void mma_bf16(float* d, const uint32_t* a, const uint32_t* b) {
    asm volatile(
        "mma.sync.aligned.m16n8k16.row.col.f32.bf16.bf16.f32 "
        "{%0,%1,%2,%3}, {%4,%5,%6,%7}, {%8,%9}, {%0,%1,%2,%3};"
        : "+f"(d[0]), "+f"(d[1]), "+f"(d[2]), "+f"(d[3])
        : "r"(a[0]), "r"(a[1]), "r"(a[2]), "r"(a[3]), "r"(b[0]), "r"(b[1]));
}
#define LDSM_X4_T(r0, r1, r2, r3, addr) \
    asm volatile("ldmatrix.sync.aligned.m8n8.x4.trans.shared.b16 {%0,%1,%2,%3}, [%4];" \
        : "=r"(r0), "=r"(r1), "=r"(r2), "=r"(r3) : "r"(addr))
#define CP_ASYNC(dst, src) \
    asm volatile("cp.async.cg.shared.global [%0], [%1], 16;" :: "r"(dst), "l"(src))
#define CP_COMMIT() asm volatile("cp.async.commit_group;" ::: "memory")
#define CP_WAIT1()  asm volatile("cp.async.wait_group 1;" ::: "memory")

// k32 bf16 tile = two k16 subtiles of 4KB. Within a subtile [16 k][128 mn]:
// row = 256B = 16 chunks of 16B; chunk' = chunk ^ (k&7). Conflict-free for
// cp.async writes and ldmatrix reads.
__device__ __forceinline__ void cp_tile32(uint32_t dstA, uint32_t dstB,
                                          const __nv_bfloat16* __restrict__ srcA, int ldA,
                                          const __nv_bfloat16* __restrict__ srcB, int ldB,
                                          int tid) {
    int k = tid >> 4;          // 0..15
    int j = tid & 15;          // chunk 0..15
    uint32_t off = (uint32_t)((k << 8) + ((j ^ (k & 7)) << 4));
#pragma unroll
    for (int h = 0; h < 2; h++) {
        uint32_t o = off + (uint32_t)(h << 12);
        CP_ASYNC(dstA + o, srcA + (size_t)(h * 16 + k) * ldA + j * 8);
        CP_ASYNC(dstB + o, srcB + (size_t)(h * 16 + k) * ldB + j * 8);
    }
}

// ---------------------------------------------------------------------------
// Kernel 0: W1 + W2 f32 -> bf16 in one launch
// ---------------------------------------------------------------------------
__global__ void f2bf_kernel(const float4* __restrict__ in1, const float4* __restrict__ in2,
                            uint2* __restrict__ out1, uint2* __restrict__ out2, int n4) {
    int i = blockIdx.x * blockDim.x + threadIdx.x;
    const float4* src; uint2* dst; int idx;
    if (i < n4)      { src = in1; dst = out1; idx = i; }
    else             { src = in2; dst = out2; idx = i - n4; if (idx >= n4) return; }
    float4 v = src[idx];
    __nv_bfloat162 lo = __floats2bfloat162_rn(v.x, v.y);
    __nv_bfloat162 hi = __floats2bfloat162_rn(v.z, v.w);
    dst[idx] = make_uint2(*(uint32_t*)&lo, *(uint32_t*)&hi);
}

// ---------------------------------------------------------------------------
// Kernel 1: per-(b,c) spatial mean + X -> bf16 conversion (same read)
// ---------------------------------------------------------------------------
__global__ void mean_kernel(const float* __restrict__ x) {
    int bc = blockIdx.x;
    const float4* p = (const float4*)(x + (size_t)bc * PP);
    float4 v = p[threadIdx.x];
    __nv_bfloat162 lo = __floats2bfloat162_rn(v.x, v.y);
    __nv_bfloat162 hi = __floats2bfloat162_rn(v.z, v.w);
    uint2* xb = (uint2*)(&g_Xbf[0][0][0] + (size_t)bc * PP);
    xb[threadIdx.x] = make_uint2(*(uint32_t*)&lo, *(uint32_t*)&hi);

    float s = v.x + v.y + v.z + v.w;
#pragma unroll
    for (int o = 16; o; o >>= 1) s += __shfl_down_sync(0xffffffffu, s, o);
    __shared__ float ws[8];
    if ((threadIdx.x & 31) == 0) ws[threadIdx.x >> 5] = s;
    __syncthreads();
    if (threadIdx.x == 0) {
        float t = 0.f;
#pragma unroll
        for (int i = 0; i < 8; i++) t += ws[i];
        g_mean[bc >> 9][bc & 511] = t * (1.0f / PP);
    }
}

// ---------------------------------------------------------------------------
// Kernel 2: gate — warp per 4 (b,e) logits, fp32 softmax, top-2, scales only
// ---------------------------------------------------------------------------
__global__ void gate_kernel(const float* __restrict__ Wg, const float* __restrict__ bg,
                            const float* __restrict__ kk) {
    __shared__ float sl[BB][EE];
    int t = threadIdx.x;
    int w = t >> 5, lane = t & 31;
#pragma unroll
    for (int q = 0; q < 4; q++) {
        int pe = w * 4 + q;            // 0..63
        int b = pe >> 3, e = pe & 7;
        float acc = 0.f;
        for (int c = lane; c < CC; c += 32)
            acc = fmaf(g_mean[b][c], Wg[c * EE + e], acc);
#pragma unroll
        for (int o = 16; o; o >>= 1) acc += __shfl_down_sync(0xffffffffu, acc, o);
        if (lane == 0) sl[b][e] = acc + bg[e];
    }
    __syncthreads();
    if (t < BB) {
        int b = t;
        float m = -1e30f;
#pragma unroll
        for (int e = 0; e < EE; e++) m = fmaxf(m, sl[b][e]);
        float wv[EE]; float sum = 0.f;
#pragma unroll
        for (int e = 0; e < EE; e++) { wv[e] = expf(sl[b][e] - m); sum += wv[e]; }
        float inv = 1.0f / sum;
#pragma unroll
        for (int e = 0; e < EE; e++) wv[e] *= inv;
        int i0 = 0;
#pragma unroll
        for (int e = 1; e < EE; e++) if (wv[e] > wv[i0]) i0 = e;
        int i1 = (i0 == 0) ? 1 : 0;
#pragma unroll
        for (int e = 0; e < EE; e++) { if (e == i0 || e == i1) continue; if (wv[e] > wv[i1]) i1 = e; }
        float kb = kk[b];
        g_expert[b][0] = i0; g_expert[b][1] = i1;
        g_scale[b][0]  = wv[i0] * kb; g_scale[b][1] = wv[i1] * kb;
    }
}

// ---------------------------------------------------------------------------
// GEMM core fragment step for one k16 subtile
// ---------------------------------------------------------------------------
__device__ __forceinline__ void compute_k16(uint32_t sA, uint32_t sB,
                                            int warp_m, int warp_n, int lane,
                                            float acc[4][4][4]) {
    int kA = (lane & 7) | ((lane & 16) >> 1);
    int mh = (lane & 8) >> 3;
    uint32_t a[4][4];
#pragma unroll
    for (int mt = 0; mt < 4; mt++) {
        int chunk = ((warp_m * 64 + mt * 16) >> 3) + mh;
        uint32_t addr = sA + (uint32_t)((kA << 8) + ((chunk ^ (kA & 7)) << 4));
        LDSM_X4_T(a[mt][0], a[mt][1], a[mt][2], a[mt][3], addr);
    }
    int kB = (lane & 7) | (lane & 8);
    int nh = (lane & 16) >> 1;
    uint32_t bfr[2][4];
#pragma unroll
    for (int ntp = 0; ntp < 2; ntp++) {
        int chunk = (warp_n * 32 + ntp * 16 + nh) >> 3;
        uint32_t addr = sB + (uint32_t)((kB << 8) + ((chunk ^ (kB & 7)) << 4));
        LDSM_X4_T(bfr[ntp][0], bfr[ntp][1], bfr[ntp][2], bfr[ntp][3], addr);
    }
#pragma unroll
    for (int mt = 0; mt < 4; mt++)
#pragma unroll
        for (int nt = 0; nt < 4; nt++)
            mma_bf16(acc[mt][nt], a[mt], &bfr[nt >> 1][(nt & 1) << 1]);
}

// ---------------------------------------------------------------------------
// Kernel 3: GEMM1  H[d,p] = s * gelu(sum_c W1[e][c][d] X[b][c][p] + b1[e][d])
// 128x128 tile, K-tile 32, 3-stage cp.async pipeline.
// ---------------------------------------------------------------------------
__global__ __launch_bounds__(256, 2)
void gemm1_mma(const float* __restrict__ b1v) {
    __shared__ __align__(256) char smA[3][8192];
    __shared__ __align__(256) char smB[3][8192];

    const int tid = threadIdx.x;
    const int wid = tid >> 5, lane = tid & 31;
    const int warp_m = wid >> 2, warp_n = wid & 3;

    const int pair = blockIdx.y;
    const int b = pair >> 1, slot = pair & 1;
    const int e = g_expert[b][slot];
    const float s = g_scale[b][slot];
    const int td = (blockIdx.x >> 3) << 7;
    const int tp = (blockIdx.x & 7) << 7;

    const __nv_bfloat16* Abase = &g_W1bf[e][0][0] + td;   // rows c (ld DH), cols d
    const __nv_bfloat16* Bbase = &g_Xbf[b][0][0] + tp;    // rows c (ld PP), cols p

    uint32_t sa[3], sb[3];
#pragma unroll
    for (int i = 0; i < 3; i++) { sa[i] = smem_u32(smA[i]); sb[i] = smem_u32(smB[i]); }

    const int KT = CC / 32;   // 16
    cp_tile32(sa[0], sb[0], Abase, DH, Bbase, PP, tid); CP_COMMIT();
    cp_tile32(sa[1], sb[1], Abase + (size_t)32 * DH, DH, Bbase + (size_t)32 * PP, PP, tid); CP_COMMIT();

    float acc[4][4][4];
#pragma unroll
    for (int i = 0; i < 4; i++)
#pragma unroll
        for (int j = 0; j < 4; j++)
#pragma unroll
            for (int q = 0; q < 4; q++) acc[i][j][q] = 0.f;

#pragma unroll 1
    for (int kt = 0; kt < KT; kt++) {
        CP_WAIT1();
        __syncthreads();
        if (kt + 2 < KT) {
            int st = (kt + 2) % 3;
            cp_tile32(sa[st], sb[st],
                      Abase + (size_t)((kt + 2) * 32) * DH, DH,
                      Bbase + (size_t)((kt + 2) * 32) * PP, PP, tid);
        }
        CP_COMMIT();
        int st = kt % 3;
        compute_k16(sa[st], sb[st], warp_m, warp_n, lane, acc);
        compute_k16(sa[st] + 4096, sb[st] + 4096, warp_m, warp_n, lane, acc);
        __syncthreads();
    }

    // epilogue: bias + exact gelu + scale -> g_Hbf (bf16)
    const int mrow = lane >> 2;
    const int ncol = (lane & 3) << 1;
    __nv_bfloat16* Hbase = &g_Hbf[b][slot][0][0];
#pragma unroll
    for (int mt = 0; mt < 4; mt++) {
#pragma unroll
        for (int h = 0; h < 2; h++) {
            int d = td + warp_m * 64 + mt * 16 + mrow + h * 8;
            float bias = b1v[e * DH + d];
            __nv_bfloat16* Hrow = Hbase + (size_t)d * PP + tp + warp_n * 32;
#pragma unroll
            for (int nt = 0; nt < 4; nt++) {
                float x0 = acc[mt][nt][h * 2 + 0] + bias;
                float x1 = acc[mt][nt][h * 2 + 1] + bias;
                float o0 = s * (0.5f * x0 * (1.0f + erff(x0 * 0.70710678118654752f)));
                float o1 = s * (0.5f * x1 * (1.0f + erff(x1 * 0.70710678118654752f)));
                __nv_bfloat162 pk = __floats2bfloat162_rn(o0, o1);
                *(uint32_t*)(Hrow + nt * 8 + ncol) = *(uint32_t*)&pk;
            }
        }
    }
}

// ---------------------------------------------------------------------------
// Kernel 4: GEMM2  out = X + (s0 b2[e0] + s1 b2[e1]) + sum_slot W2[e]^T H
// K = 2048, K-tile 32.
// ---------------------------------------------------------------------------
__global__ __launch_bounds__(256, 2)
void gemm2_mma(const float* __restrict__ X, const float* __restrict__ b2,
               float* __restrict__ out) {
    __shared__ __align__(256) char smA[3][8192];
    __shared__ __align__(256) char smB[3][8192];

    const int tid = threadIdx.x;
    const int wid = tid >> 5, lane = tid & 31;
    const int warp_m = wid >> 2, warp_n = wid & 3;

    const int b = blockIdx.y;
    const int tc = (blockIdx.x >> 3) << 7;
    const int tp = (blockIdx.x & 7) << 7;
    const int e0 = g_expert[b][0], e1 = g_expert[b][1];
    const float s0 = g_scale[b][0], s1 = g_scale[b][1];

    const __nv_bfloat16* A0 = &g_W2bf[e0][0][0] + tc;   // rows d (ld CC), cols c
    const __nv_bfloat16* A1 = &g_W2bf[e1][0][0] + tc;
    const __nv_bfloat16* H0 = &g_Hbf[b][0][0][0] + tp;  // rows d (ld PP), cols p
    const __nv_bfloat16* H1 = &g_Hbf[b][1][0][0] + tp;

    uint32_t sa[3], sb[3];
#pragma unroll
    for (int i = 0; i < 3; i++) { sa[i] = smem_u32(smA[i]); sb[i] = smem_u32(smB[i]); }

    const int KT = 2 * DH / 32;   // 64
#define SRC_A(kt) ((((kt) >> 5) ? A1 : A0) + (size_t)(((kt) & 31) * 32) * CC)
#define SRC_B(kt) ((((kt) >> 5) ? H1 : H0) + (size_t)(((kt) & 31) * 32) * PP)

    cp_tile32(sa[0], sb[0], SRC_A(0), CC, SRC_B(0), PP, tid); CP_COMMIT();
    cp_tile32(sa[1], sb[1], SRC_A(1), CC, SRC_B(1), PP, tid); CP_COMMIT();

    float acc[4][4][4];
#pragma unroll
    for (int i = 0; i < 4; i++)
#pragma unroll
        for (int j = 0; j < 4; j++)
#pragma unroll
            for (int q = 0; q < 4; q++) acc[i][j][q] = 0.f;

#pragma unroll 1
    for (int kt = 0; kt < KT; kt++) {
        CP_WAIT1();
        __syncthreads();
        if (kt + 2 < KT) {
            int st = (kt + 2) % 3;
            cp_tile32(sa[st], sb[st], SRC_A(kt + 2), CC, SRC_B(kt + 2), PP, tid);
        }
        CP_COMMIT();
        int st = kt % 3;
        compute_k16(sa[st], sb[st], warp_m, warp_n, lane, acc);
        compute_k16(sa[st] + 4096, sb[st] + 4096, warp_m, warp_n, lane, acc);
        __syncthreads();
    }
#undef SRC_A
#undef SRC_B

    // epilogue: residual (fp32) + combined b2 bias (computed inline)
    const int mrow = lane >> 2;
    const int ncol = (lane & 3) << 1;
#pragma unroll
    for (int mt = 0; mt < 4; mt++) {
#pragma unroll
        for (int h = 0; h < 2; h++) {
            int c = tc + warp_m * 64 + mt * 16 + mrow + h * 8;
            float cb = s0 * b2[e0 * CC + c] + s1 * b2[e1 * CC + c];
            size_t rowbase = ((size_t)(b * CC + c)) * PP + tp + warp_n * 32;
#pragma unroll
            for (int nt = 0; nt < 4; nt++) {
                float2 xin = *(const float2*)(X + rowbase + nt * 8 + ncol);
                float2 o;
                o.x = xin.x + cb + acc[mt][nt][h * 2 + 0];
                o.y = xin.y + cb + acc[mt][nt][h * 2 + 1];
                *(float2*)(out + rowbase + nt * 8 + ncol) = o;
            }
        }
    }
}

// ---------------------------------------------------------------------------
extern "C" void kernel_launch(void* const* d_in, const int* in_sizes, int n_in,
                              void* d_out, int out_size) {
    const float* inputs = (const float*)d_in[0];
    const float* kk     = (const float*)d_in[1];
    const float* Wg     = (const float*)d_in[2];
    const float* bg     = (const float*)d_in[3];
    const float* W1     = (const float*)d_in[4];
    const float* b1     = (const float*)d_in[5];
    const float* W2     = (const float*)d_in[6];
    const float* b2     = (const float*)d_in[7];
    float* out = (float*)d_out;

    __nv_bfloat16 *w1bf_p, *w2bf_p;
    cudaGetSymbolAddress((void**)&w1bf_p, g_W1bf);
    cudaGetSymbolAddress((void**)&w2bf_p, g_W2bf);

    const int n4 = EE * CC * DH / 4;   // 1M float4 per weight tensor
    f2bf_kernel<<<(2 * n4 + 255) / 256, 256>>>((const float4*)W1, (const float4*)W2,
                                               (uint2*)w1bf_p, (uint2*)w2bf_p, n4);
    mean_kernel<<<BB * CC, 256>>>(inputs);
    gate_kernel<<<1, 512>>>(Wg, bg, kk);
    gemm1_mma<<<dim3(64, 16), 256>>>(b1);
    gemm2_mma<<<dim3(32, 8), 256>>>(inputs, b2, out);
}

// round 6
// speedup vs baseline: 5.9011x; 1.0760x over previous
#include <cuda_runtime.h>
#include <cuda_bf16.h>
#include <math.h>
#include <stdint.h>

#define BB 8
#define CC 512
#define PP 1024   // H*W
#define EE 8
#define DH 1024

// Scratch (module-load allocation; none at runtime)
__device__ float g_mean[BB][CC];
__device__ float g_scale[BB][2];
__device__ int   g_expert[BB][2];
__device__ __nv_bfloat16 g_Xbf[BB][CC][PP];        // 8 MB
__device__ __nv_bfloat16 g_W1bf[EE][CC][DH];       // 8 MB
__device__ __nv_bfloat16 g_W2bf[EE][DH][CC];       // 8 MB
__device__ __nv_bfloat16 g_Hbf[BB][2][DH][PP];     // 32 MB

// ---------------------------------------------------------------------------
// helpers
// ---------------------------------------------------------------------------
__device__ __forceinline__ uint32_t smem_u32(const void* p) {
    uint32_t a;
    asm("{ .reg .u64 t; cvta.to.shared.u64 t, %1; cvt.u32.u64 %0, t; }" : "=r"(a) : "l"(p));
    return a;
}
__device__ __forceinline__ void mma_bf16(float* d, const uint32_t* a, const uint32_t* b) {
    asm volatile(
        "mma.sync.aligned.m16n8k16.row.col.f32.bf16.bf16.f32 "
        "{%0,%1,%2,%3}, {%4,%5,%6,%7}, {%8,%9}, {%0,%1,%2,%3};"
        : "+f"(d[0]), "+f"(d[1]), "+f"(d[2]), "+f"(d[3])
        : "r"(a[0]), "r"(a[1]), "r"(a[2]), "r"(a[3]), "r"(b[0]), "r"(b[1]));
}
#define LDSM_X4_T(r0, r1, r2, r3, addr) \
    asm volatile("ldmatrix.sync.aligned.m8n8.x4.trans.shared.b16 {%0,%1,%2,%3}, [%4];" \
        : "=r"(r0), "=r"(r1), "=r"(r2), "=r"(r3) : "r"(addr))
#define CP_ASYNC(dst, src) \
    asm volatile("cp.async.cg.shared.global [%0], [%1], 16;" :: "r"(dst), "l"(src))
#define CP_COMMIT() asm volatile("cp.async.commit_group;" ::: "memory")
#define CP_WAIT1()  asm volatile("cp.async.wait_group 1;" ::: "memory")

// Per-thread loop-invariant LDSM offsets (relative to k32-tile smem base).
// k32 tile = two 4KB k16 subtiles; subtile row = 256B = 16 chunks of 16B,
// chunk' = chunk ^ (k & 7)  — conflict-free for cp.async and ldmatrix.
struct LdsmOff { uint32_t a[4]; uint32_t b[2]; };
__device__ __forceinline__ LdsmOff make_off(int warp_m, int warp_n, int lane) {
    LdsmOff o;
    int kA = (lane & 7) | ((lane & 16) >> 1);
    int mh = (lane & 8) >> 3;
#pragma unroll
    for (int mt = 0; mt < 4; mt++) {
        int chunk = ((warp_m * 64 + mt * 16) >> 3) + mh;
        o.a[mt] = (uint32_t)((kA << 8) + ((chunk ^ (kA & 7)) << 4));
    }
    int kB = (lane & 7) | (lane & 8);
    int nh = (lane & 16) >> 1;
#pragma unroll
    for (int ntp = 0; ntp < 2; ntp++) {
        int chunk = (warp_n * 32 + ntp * 16 + nh) >> 3;
        o.b[ntp] = (uint32_t)((kB << 8) + ((chunk ^ (kB & 7)) << 4));
    }
    return o;
}

// one k16 subtile: 6 LDSM + 16 MMA, addresses = base + hoisted offset
__device__ __forceinline__ void compute_k16(uint32_t sA, uint32_t sB,
                                            const LdsmOff& o, float acc[4][4][4]) {
    uint32_t a[4][4];
#pragma unroll
    for (int mt = 0; mt < 4; mt++)
        LDSM_X4_T(a[mt][0], a[mt][1], a[mt][2], a[mt][3], sA + o.a[mt]);
    uint32_t bfr[2][4];
#pragma unroll
    for (int ntp = 0; ntp < 2; ntp++)
        LDSM_X4_T(bfr[ntp][0], bfr[ntp][1], bfr[ntp][2], bfr[ntp][3], sB + o.b[ntp]);
#pragma unroll
    for (int mt = 0; mt < 4; mt++)
#pragma unroll
        for (int nt = 0; nt < 4; nt++)
            mma_bf16(acc[mt][nt], a[mt], &bfr[nt >> 1][(nt & 1) << 1]);
}

// cp.async one k32 tile; pA/pB already carry the per-thread offset (k*ld + j*8)
__device__ __forceinline__ void cp_k32(uint32_t dstA, uint32_t dstB, uint32_t off,
                                       const __nv_bfloat16* pA, int ldA,
                                       const __nv_bfloat16* pB, int ldB) {
    CP_ASYNC(dstA + off, pA);
    CP_ASYNC(dstB + off, pB);
    CP_ASYNC(dstA + off + 4096, pA + (size_t)16 * ldA);
    CP_ASYNC(dstB + off + 4096, pB + (size_t)16 * ldB);
}

// ---------------------------------------------------------------------------
// Kernel 0: W1 + W2 f32 -> bf16 in one launch
// ---------------------------------------------------------------------------
__global__ void f2bf_kernel(const float4* __restrict__ in1, const float4* __restrict__ in2,
                            uint2* __restrict__ out1, uint2* __restrict__ out2, int n4) {
    int i = blockIdx.x * blockDim.x + threadIdx.x;
    const float4* src; uint2* dst; int idx;
    if (i < n4)      { src = in1; dst = out1; idx = i; }
    else             { src = in2; dst = out2; idx = i - n4; if (idx >= n4) return; }
    float4 v = src[idx];
    __nv_bfloat162 lo = __floats2bfloat162_rn(v.x, v.y);
    __nv_bfloat162 hi = __floats2bfloat162_rn(v.z, v.w);
    dst[idx] = make_uint2(*(uint32_t*)&lo, *(uint32_t*)&hi);
}

// ---------------------------------------------------------------------------
// Kernel 1: per-(b,c) spatial mean + X -> bf16 conversion (same read)
// ---------------------------------------------------------------------------
__global__ void mean_kernel(const float* __restrict__ x) {
    int bc = blockIdx.x;
    const float4* p = (const float4*)(x + (size_t)bc * PP);
    float4 v = p[threadIdx.x];
    __nv_bfloat162 lo = __floats2bfloat162_rn(v.x, v.y);
    __nv_bfloat162 hi = __floats2bfloat162_rn(v.z, v.w);
    uint2* xb = (uint2*)(&g_Xbf[0][0][0] + (size_t)bc * PP);
    xb[threadIdx.x] = make_uint2(*(uint32_t*)&lo, *(uint32_t*)&hi);

    float s = v.x + v.y + v.z + v.w;
#pragma unroll
    for (int o = 16; o; o >>= 1) s += __shfl_down_sync(0xffffffffu, s, o);
    __shared__ float ws[8];
    if ((threadIdx.x & 31) == 0) ws[threadIdx.x >> 5] = s;
    __syncthreads();
    if (threadIdx.x == 0) {
        float t = 0.f;
#pragma unroll
        for (int i = 0; i < 8; i++) t += ws[i];
        g_mean[bc >> 9][bc & 511] = t * (1.0f / PP);
    }
}

// ---------------------------------------------------------------------------
// Kernel 2: gate
// ---------------------------------------------------------------------------
__global__ void gate_kernel(const float* __restrict__ Wg, const float* __restrict__ bg,
                            const float* __restrict__ kk) {
    __shared__ float sl[BB][EE];
    int t = threadIdx.x;
    int w = t >> 5, lane = t & 31;
#pragma unroll
    for (int q = 0; q < 4; q++) {
        int pe = w * 4 + q;
        int b = pe >> 3, e = pe & 7;
        float acc = 0.f;
        for (int c = lane; c < CC; c += 32)
            acc = fmaf(g_mean[b][c], Wg[c * EE + e], acc);
#pragma unroll
        for (int o = 16; o; o >>= 1) acc += __shfl_down_sync(0xffffffffu, acc, o);
        if (lane == 0) sl[b][e] = acc + bg[e];
    }
    __syncthreads();
    if (t < BB) {
        int b = t;
        float m = -1e30f;
#pragma unroll
        for (int e = 0; e < EE; e++) m = fmaxf(m, sl[b][e]);
        float wv[EE]; float sum = 0.f;
#pragma unroll
        for (int e = 0; e < EE; e++) { wv[e] = expf(sl[b][e] - m); sum += wv[e]; }
        float inv = 1.0f / sum;
#pragma unroll
        for (int e = 0; e < EE; e++) wv[e] *= inv;
        int i0 = 0;
#pragma unroll
        for (int e = 1; e < EE; e++) if (wv[e] > wv[i0]) i0 = e;
        int i1 = (i0 == 0) ? 1 : 0;
#pragma unroll
        for (int e = 0; e < EE; e++) { if (e == i0 || e == i1) continue; if (wv[e] > wv[i1]) i1 = e; }
        float kb = kk[b];
        g_expert[b][0] = i0; g_expert[b][1] = i1;
        g_scale[b][0]  = wv[i0] * kb; g_scale[b][1] = wv[i1] * kb;
    }
}

// ---------------------------------------------------------------------------
// Kernel 3: GEMM1  H[d,p] = s * gelu(sum_c W1[e][c][d] X[b][c][p] + b1[e][d])
// ---------------------------------------------------------------------------
__global__ __launch_bounds__(256, 2)
void gemm1_mma(const float* __restrict__ b1v) {
    __shared__ __align__(256) char smA[3][8192];
    __shared__ __align__(256) char smB[3][8192];

    const int tid = threadIdx.x;
    const int wid = tid >> 5, lane = tid & 31;
    const LdsmOff off = make_off(wid >> 2, wid & 3, lane);

    const int pair = blockIdx.y;
    const int b = pair >> 1, slot = pair & 1;
    const int e = g_expert[b][slot];
    const float s = g_scale[b][slot];
    const int td = (blockIdx.x >> 3) << 7;
    const int tp = (blockIdx.x & 7) << 7;

    // per-thread cp.async source pointers / dst offset
    const int ck = tid >> 4;           // 0..15
    const int cj = tid & 15;           // 0..15
    const uint32_t coff = (uint32_t)((ck << 8) + ((cj ^ (ck & 7)) << 4));
    const __nv_bfloat16* pA = &g_W1bf[e][0][0] + td + (size_t)ck * DH + cj * 8;
    const __nv_bfloat16* pB = &g_Xbf[b][0][0] + tp + (size_t)ck * PP + cj * 8;

    uint32_t sa[3], sb[3];
#pragma unroll
    for (int i = 0; i < 3; i++) { sa[i] = smem_u32(smA[i]); sb[i] = smem_u32(smB[i]); }

    const int KT = CC / 32;   // 16
    cp_k32(sa[0], sb[0], coff, pA, DH, pB, PP); CP_COMMIT();
    pA += (size_t)32 * DH; pB += (size_t)32 * PP;
    cp_k32(sa[1], sb[1], coff, pA, DH, pB, PP); CP_COMMIT();
    pA += (size_t)32 * DH; pB += (size_t)32 * PP;

    float acc[4][4][4];
#pragma unroll
    for (int i = 0; i < 4; i++)
#pragma unroll
        for (int j = 0; j < 4; j++)
#pragma unroll
            for (int q = 0; q < 4; q++) acc[i][j][q] = 0.f;

    int st = 0, pf = 2;
#pragma unroll 1
    for (int kt = 0; kt < KT; kt++) {
        CP_WAIT1();
        __syncthreads();
        if (kt + 2 < KT) {
            cp_k32(sa[pf], sb[pf], coff, pA, DH, pB, PP);
            pA += (size_t)32 * DH; pB += (size_t)32 * PP;
        }
        CP_COMMIT();
        compute_k16(sa[st], sb[st], off, acc);
        compute_k16(sa[st] + 4096, sb[st] + 4096, off, acc);
        __syncthreads();
        if (++st == 3) st = 0;
        if (++pf == 3) pf = 0;
    }

    // epilogue: bias + exact gelu + scale -> g_Hbf (bf16)
    const int warp_m = wid >> 2, warp_n = wid & 3;
    const int mrow = lane >> 2;
    const int ncol = (lane & 3) << 1;
    __nv_bfloat16* Hbase = &g_Hbf[b][slot][0][0];
#pragma unroll
    for (int mt = 0; mt < 4; mt++) {
#pragma unroll
        for (int h = 0; h < 2; h++) {
            int d = td + warp_m * 64 + mt * 16 + mrow + h * 8;
            float bias = b1v[e * DH + d];
            __nv_bfloat16* Hrow = Hbase + (size_t)d * PP + tp + warp_n * 32;
#pragma unroll
            for (int nt = 0; nt < 4; nt++) {
                float x0 = acc[mt][nt][h * 2 + 0] + bias;
                float x1 = acc[mt][nt][h * 2 + 1] + bias;
                float o0 = s * (0.5f * x0 * (1.0f + erff(x0 * 0.70710678118654752f)));
                float o1 = s * (0.5f * x1 * (1.0f + erff(x1 * 0.70710678118654752f)));
                __nv_bfloat162 pk = __floats2bfloat162_rn(o0, o1);
                *(uint32_t*)(Hrow + nt * 8 + ncol) = *(uint32_t*)&pk;
            }
        }
    }
}

// ---------------------------------------------------------------------------
// Kernel 4: GEMM2  out = X + (s0 b2[e0] + s1 b2[e1]) + sum_slot W2[e]^T H
// ---------------------------------------------------------------------------
__global__ __launch_bounds__(256, 2)
void gemm2_mma(const float* __restrict__ X, const float* __restrict__ b2,
               float* __restrict__ out) {
    __shared__ __align__(256) char smA[3][8192];
    __shared__ __align__(256) char smB[3][8192];

    const int tid = threadIdx.x;
    const int wid = tid >> 5, lane = tid & 31;
    const LdsmOff off = make_off(wid >> 2, wid & 3, lane);

    const int b = blockIdx.y;
    const int tc = (blockIdx.x >> 3) << 7;
    const int tp = (blockIdx.x & 7) << 7;
    const int e0 = g_expert[b][0], e1 = g_expert[b][1];
    const float s0 = g_scale[b][0], s1 = g_scale[b][1];

    const int ck = tid >> 4;
    const int cj = tid & 15;
    const uint32_t coff = (uint32_t)((ck << 8) + ((cj ^ (ck & 7)) << 4));
    const size_t tbA = (size_t)ck * CC + cj * 8;
    const size_t tbB = (size_t)ck * PP + cj * 8;
    const __nv_bfloat16* pA = &g_W2bf[e0][0][0] + tc + tbA;
    const __nv_bfloat16* pB = &g_Hbf[b][0][0][0] + tp + tbB;
    const __nv_bfloat16* A1 = &g_W2bf[e1][0][0] + tc + tbA;
    const __nv_bfloat16* H1 = &g_Hbf[b][1][0][0] + tp + tbB;

    uint32_t sa[3], sb[3];
#pragma unroll
    for (int i = 0; i < 3; i++) { sa[i] = smem_u32(smA[i]); sb[i] = smem_u32(smB[i]); }

    const int KT = 2 * DH / 32;   // 64
    cp_k32(sa[0], sb[0], coff, pA, CC, pB, PP); CP_COMMIT();
    pA += (size_t)32 * CC; pB += (size_t)32 * PP;
    cp_k32(sa[1], sb[1], coff, pA, CC, pB, PP); CP_COMMIT();
    pA += (size_t)32 * CC; pB += (size_t)32 * PP;

    float acc[4][4][4];
#pragma unroll
    for (int i = 0; i < 4; i++)
#pragma unroll
        for (int j = 0; j < 4; j++)
#pragma unroll
            for (int q = 0; q < 4; q++) acc[i][j][q] = 0.f;

    int st = 0, pf = 2;
#pragma unroll 1
    for (int kt = 0; kt < KT; kt++) {
        CP_WAIT1();
        __syncthreads();
        if (kt + 2 < KT) {
            if (kt + 2 == 32) { pA = A1; pB = H1; }   // slot switch
            cp_k32(sa[pf], sb[pf], coff, pA, CC, pB, PP);
            pA += (size_t)32 * CC; pB += (size_t)32 * PP;
        }
        CP_COMMIT();
        compute_k16(sa[st], sb[st], off, acc);
        compute_k16(sa[st] + 4096, sb[st] + 4096, off, acc);
        __syncthreads();
        if (++st == 3) st = 0;
        if (++pf == 3) pf = 0;
    }

    // epilogue: residual (fp32) + combined b2 bias inline
    const int warp_m = wid >> 2, warp_n = wid & 3;
    const int mrow = lane >> 2;
    const int ncol = (lane & 3) << 1;
#pragma unroll
    for (int mt = 0; mt < 4; mt++) {
#pragma unroll
        for (int h = 0; h < 2; h++) {
            int c = tc + warp_m * 64 + mt * 16 + mrow + h * 8;
            float cb = s0 * b2[e0 * CC + c] + s1 * b2[e1 * CC + c];
            size_t rowbase = ((size_t)(b * CC + c)) * PP + tp + warp_n * 32;
#pragma unroll
            for (int nt = 0; nt < 4; nt++) {
                float2 xin = *(const float2*)(X + rowbase + nt * 8 + ncol);
                float2 o;
                o.x = xin.x + cb + acc[mt][nt][h * 2 + 0];
                o.y = xin.y + cb + acc[mt][nt][h * 2 + 1];
                *(float2*)(out + rowbase + nt * 8 + ncol) = o;
            }
        }
    }
}

// ---------------------------------------------------------------------------
extern "C" void kernel_launch(void* const* d_in, const int* in_sizes, int n_in,
                              void* d_out, int out_size) {
    const float* inputs = (const float*)d_in[0];
    const float* kk     = (const float*)d_in[1];
    const float* Wg     = (const float*)d_in[2];
    const float* bg     = (const float*)d_in[3];
    const float* W1     = (const float*)d_in[4];
    const float* b1     = (const float*)d_in[5];
    const float* W2     = (const float*)d_in[6];
    const float* b2     = (const float*)d_in[7];
    float* out = (float*)d_out;

    __nv_bfloat16 *w1bf_p, *w2bf_p;
    cudaGetSymbolAddress((void**)&w1bf_p, g_W1bf);
    cudaGetSymbolAddress((void**)&w2bf_p, g_W2bf);

    const int n4 = EE * CC * DH / 4;
    f2bf_kernel<<<(2 * n4 + 255) / 256, 256>>>((const float4*)W1, (const float4*)W2,
                                               (uint2*)w1bf_p, (uint2*)w2bf_p, n4);
    mean_kernel<<<BB * CC, 256>>>(inputs);
    gate_kernel<<<1, 512>>>(Wg, bg, kk);
    gemm1_mma<<<dim3(64, 16), 256>>>(b1);
    gemm2_mma<<<dim3(32, 8), 256>>>(inputs, b2, out);
}

// round 7
// speedup vs baseline: 5.9039x; 1.0005x over previous
#include <cuda_runtime.h>
#include <cuda_bf16.h>
#include <math.h>
#include <stdint.h>

#define BB 8
#define CC 512
#define PP 1024   // H*W
#define EE 8
#define DH 1024

// Scratch (module-load allocation; none at runtime)
__device__ float g_mean[BB][CC];
__device__ float g_scale[BB][2];
__device__ int   g_expert[BB][2];
__device__ __nv_bfloat16 g_Xbf[BB][CC][PP];        // 8 MB
__device__ __nv_bfloat16 g_W1bf[EE][CC][DH];       // 8 MB
__device__ __nv_bfloat16 g_W2bf[EE][DH][CC];       // 8 MB
__device__ __nv_bfloat16 g_Hbf[BB][2][DH][PP];     // 32 MB

// ---------------------------------------------------------------------------
// helpers
// ---------------------------------------------------------------------------
__device__ __forceinline__ uint32_t smem_u32(const void* p) {
    uint32_t a;
    asm("{ .reg .u64 t; cvta.to.shared.u64 t, %1; cvt.u32.u64 %0, t; }" : "=r"(a) : "l"(p));
    return a;
}
__device__ __forceinline__ void mma_bf16(float* d, const uint32_t* a, const uint32_t* b) {
    asm volatile(
        "mma.sync.aligned.m16n8k16.row.col.f32.bf16.bf16.f32 "
        "{%0,%1,%2,%3}, {%4,%5,%6,%7}, {%8,%9}, {%0,%1,%2,%3};"
        : "+f"(d[0]), "+f"(d[1]), "+f"(d[2]), "+f"(d[3])
        : "r"(a[0]), "r"(a[1]), "r"(a[2]), "r"(a[3]), "r"(b[0]), "r"(b[1]));
}
#define LDSM_X4_T(r0, r1, r2, r3, addr) \
    asm volatile("ldmatrix.sync.aligned.m8n8.x4.trans.shared.b16 {%0,%1,%2,%3}, [%4];" \
        : "=r"(r0), "=r"(r1), "=r"(r2), "=r"(r3) : "r"(addr))
#define CP_ASYNC(dst, src) \
    asm volatile("cp.async.cg.shared.global [%0], [%1], 16;" :: "r"(dst), "l"(src))
#define CP_COMMIT() asm volatile("cp.async.commit_group;" ::: "memory")
#define CP_WAIT1()  asm volatile("cp.async.wait_group 1;" ::: "memory")

// Per-thread loop-invariant LDSM offsets (relative to k32-tile smem base).
// k32 tile = two 4KB k16 subtiles; subtile row = 256B = 16 chunks of 16B,
// chunk' = chunk ^ (k & 7)  — conflict-free for cp.async and ldmatrix.
struct LdsmOff { uint32_t a[4]; uint32_t b[2]; };
__device__ __forceinline__ LdsmOff make_off(int warp_m, int warp_n, int lane) {
    LdsmOff o;
    int kA = (lane & 7) | ((lane & 16) >> 1);
    int mh = (lane & 8) >> 3;
#pragma unroll
    for (int mt = 0; mt < 4; mt++) {
        int chunk = ((warp_m * 64 + mt * 16) >> 3) + mh;
        o.a[mt] = (uint32_t)((kA << 8) + ((chunk ^ (kA & 7)) << 4));
    }
    int kB = (lane & 7) | (lane & 8);
    int nh = (lane & 16) >> 1;
#pragma unroll
    for (int ntp = 0; ntp < 2; ntp++) {
        int chunk = (warp_n * 32 + ntp * 16 + nh) >> 3;
        o.b[ntp] = (uint32_t)((kB << 8) + ((chunk ^ (kB & 7)) << 4));
    }
    return o;
}

// one k16 subtile: 6 LDSM + 16 MMA, addresses = base + hoisted offset
__device__ __forceinline__ void compute_k16(uint32_t sA, uint32_t sB,
                                            const LdsmOff& o, float acc[4][4][4]) {
    uint32_t a[4][4];
#pragma unroll
    for (int mt = 0; mt < 4; mt++)
        LDSM_X4_T(a[mt][0], a[mt][1], a[mt][2], a[mt][3], sA + o.a[mt]);
    uint32_t bfr[2][4];
#pragma unroll
    for (int ntp = 0; ntp < 2; ntp++)
        LDSM_X4_T(bfr[ntp][0], bfr[ntp][1], bfr[ntp][2], bfr[ntp][3], sB + o.b[ntp]);
#pragma unroll
    for (int mt = 0; mt < 4; mt++)
#pragma unroll
        for (int nt = 0; nt < 4; nt++)
            mma_bf16(acc[mt][nt], a[mt], &bfr[nt >> 1][(nt & 1) << 1]);
}

// cp.async one k32 tile; pA/pB already carry the per-thread offset (k*ld + j*8)
__device__ __forceinline__ void cp_k32(uint32_t dstA, uint32_t dstB, uint32_t off,
                                       const __nv_bfloat16* pA, int ldA,
                                       const __nv_bfloat16* pB, int ldB) {
    CP_ASYNC(dstA + off, pA);
    CP_ASYNC(dstB + off, pB);
    CP_ASYNC(dstA + off + 4096, pA + (size_t)16 * ldA);
    CP_ASYNC(dstB + off + 4096, pB + (size_t)16 * ldB);
}

// ---------------------------------------------------------------------------
// Kernel 0: W1 + W2 f32 -> bf16 in one launch
// ---------------------------------------------------------------------------
__global__ void f2bf_kernel(const float4* __restrict__ in1, const float4* __restrict__ in2,
                            uint2* __restrict__ out1, uint2* __restrict__ out2, int n4) {
    int i = blockIdx.x * blockDim.x + threadIdx.x;
    const float4* src; uint2* dst; int idx;
    if (i < n4)      { src = in1; dst = out1; idx = i; }
    else             { src = in2; dst = out2; idx = i - n4; if (idx >= n4) return; }
    float4 v = src[idx];
    __nv_bfloat162 lo = __floats2bfloat162_rn(v.x, v.y);
    __nv_bfloat162 hi = __floats2bfloat162_rn(v.z, v.w);
    dst[idx] = make_uint2(*(uint32_t*)&lo, *(uint32_t*)&hi);
}

// ---------------------------------------------------------------------------
// Kernel 1: per-(b,c) spatial mean + X -> bf16 conversion (same read)
// ---------------------------------------------------------------------------
__global__ void mean_kernel(const float* __restrict__ x) {
    int bc = blockIdx.x;
    const float4* p = (const float4*)(x + (size_t)bc * PP);
    float4 v = p[threadIdx.x];
    __nv_bfloat162 lo = __floats2bfloat162_rn(v.x, v.y);
    __nv_bfloat162 hi = __floats2bfloat162_rn(v.z, v.w);
    uint2* xb = (uint2*)(&g_Xbf[0][0][0] + (size_t)bc * PP);
    xb[threadIdx.x] = make_uint2(*(uint32_t*)&lo, *(uint32_t*)&hi);

    float s = v.x + v.y + v.z + v.w;
#pragma unroll
    for (int o = 16; o; o >>= 1) s += __shfl_down_sync(0xffffffffu, s, o);
    __shared__ float ws[8];
    if ((threadIdx.x & 31) == 0) ws[threadIdx.x >> 5] = s;
    __syncthreads();
    if (threadIdx.x == 0) {
        float t = 0.f;
#pragma unroll
        for (int i = 0; i < 8; i++) t += ws[i];
        g_mean[bc >> 9][bc & 511] = t * (1.0f / PP);
    }
}

// ---------------------------------------------------------------------------
// Kernel 2: gate
// ---------------------------------------------------------------------------
__global__ void gate_kernel(const float* __restrict__ Wg, const float* __restrict__ bg,
                            const float* __restrict__ kk) {
    __shared__ float sl[BB][EE];
    int t = threadIdx.x;
    int w = t >> 5, lane = t & 31;
#pragma unroll
    for (int q = 0; q < 4; q++) {
        int pe = w * 4 + q;
        int b = pe >> 3, e = pe & 7;
        float acc = 0.f;
        for (int c = lane; c < CC; c += 32)
            acc = fmaf(g_mean[b][c], Wg[c * EE + e], acc);
#pragma unroll
        for (int o = 16; o; o >>= 1) acc += __shfl_down_sync(0xffffffffu, acc, o);
        if (lane == 0) sl[b][e] = acc + bg[e];
    }
    __syncthreads();
    if (t < BB) {
        int b = t;
        float m = -1e30f;
#pragma unroll
        for (int e = 0; e < EE; e++) m = fmaxf(m, sl[b][e]);
        float wv[EE]; float sum = 0.f;
#pragma unroll
        for (int e = 0; e < EE; e++) { wv[e] = expf(sl[b][e] - m); sum += wv[e]; }
        float inv = 1.0f / sum;
#pragma unroll
        for (int e = 0; e < EE; e++) wv[e] *= inv;
        int i0 = 0;
#pragma unroll
        for (int e = 1; e < EE; e++) if (wv[e] > wv[i0]) i0 = e;
        int i1 = (i0 == 0) ? 1 : 0;
#pragma unroll
        for (int e = 0; e < EE; e++) { if (e == i0 || e == i1) continue; if (wv[e] > wv[i1]) i1 = e; }
        float kb = kk[b];
        g_expert[b][0] = i0; g_expert[b][1] = i1;
        g_scale[b][0]  = wv[i0] * kb; g_scale[b][1] = wv[i1] * kb;
    }
}

// ---------------------------------------------------------------------------
// Kernel 3: GEMM1  H[d,p] = s * gelu(sum_c W1[e][c][d] X[b][c][p] + b1[e][d])
// ---------------------------------------------------------------------------
__global__ __launch_bounds__(256, 2)
void gemm1_mma(const float* __restrict__ b1v) {
    __shared__ __align__(256) char smA[3][8192];
    __shared__ __align__(256) char smB[3][8192];

    const int tid = threadIdx.x;
    const int wid = tid >> 5, lane = tid & 31;
    const LdsmOff off = make_off(wid >> 2, wid & 3, lane);

    const int pair = blockIdx.y;
    const int b = pair >> 1, slot = pair & 1;
    const int e = g_expert[b][slot];
    const float s = g_scale[b][slot];
    const int td = (blockIdx.x >> 3) << 7;
    const int tp = (blockIdx.x & 7) << 7;

    // per-thread cp.async source pointers / dst offset
    const int ck = tid >> 4;           // 0..15
    const int cj = tid & 15;           // 0..15
    const uint32_t coff = (uint32_t)((ck << 8) + ((cj ^ (ck & 7)) << 4));
    const __nv_bfloat16* pA = &g_W1bf[e][0][0] + td + (size_t)ck * DH + cj * 8;
    const __nv_bfloat16* pB = &g_Xbf[b][0][0] + tp + (size_t)ck * PP + cj * 8;

    uint32_t sa[3], sb[3];
#pragma unroll
    for (int i = 0; i < 3; i++) { sa[i] = smem_u32(smA[i]); sb[i] = smem_u32(smB[i]); }

    const int KT = CC / 32;   // 16
    cp_k32(sa[0], sb[0], coff, pA, DH, pB, PP); CP_COMMIT();
    pA += (size_t)32 * DH; pB += (size_t)32 * PP;
    cp_k32(sa[1], sb[1], coff, pA, DH, pB, PP); CP_COMMIT();
    pA += (size_t)32 * DH; pB += (size_t)32 * PP;

    float acc[4][4][4];
#pragma unroll
    for (int i = 0; i < 4; i++)
#pragma unroll
        for (int j = 0; j < 4; j++)
#pragma unroll
            for (int q = 0; q < 4; q++) acc[i][j][q] = 0.f;

    int st = 0, pf = 2;
#pragma unroll 1
    for (int kt = 0; kt < KT; kt++) {
        CP_WAIT1();
        __syncthreads();
        if (kt + 2 < KT) {
            cp_k32(sa[pf], sb[pf], coff, pA, DH, pB, PP);
            pA += (size_t)32 * DH; pB += (size_t)32 * PP;
        }
        CP_COMMIT();
        compute_k16(sa[st], sb[st], off, acc);
        compute_k16(sa[st] + 4096, sb[st] + 4096, off, acc);
        __syncthreads();
        if (++st == 3) st = 0;
        if (++pf == 3) pf = 0;
    }

    // epilogue: bias + exact gelu + scale -> g_Hbf (bf16)
    const int warp_m = wid >> 2, warp_n = wid & 3;
    const int mrow = lane >> 2;
    const int ncol = (lane & 3) << 1;
    __nv_bfloat16* Hbase = &g_Hbf[b][slot][0][0];
#pragma unroll
    for (int mt = 0; mt < 4; mt++) {
#pragma unroll
        for (int h = 0; h < 2; h++) {
            int d = td + warp_m * 64 + mt * 16 + mrow + h * 8;
            float bias = b1v[e * DH + d];
            __nv_bfloat16* Hrow = Hbase + (size_t)d * PP + tp + warp_n * 32;
#pragma unroll
            for (int nt = 0; nt < 4; nt++) {
                float x0 = acc[mt][nt][h * 2 + 0] + bias;
                float x1 = acc[mt][nt][h * 2 + 1] + bias;
                float o0 = s * (0.5f * x0 * (1.0f + erff(x0 * 0.70710678118654752f)));
                float o1 = s * (0.5f * x1 * (1.0f + erff(x1 * 0.70710678118654752f)));
                __nv_bfloat162 pk = __floats2bfloat162_rn(o0, o1);
                *(uint32_t*)(Hrow + nt * 8 + ncol) = *(uint32_t*)&pk;
            }
        }
    }
}

// ---------------------------------------------------------------------------
// Kernel 4: GEMM2  out = X + (s0 b2[e0] + s1 b2[e1]) + sum_slot W2[e]^T H
// ---------------------------------------------------------------------------
__global__ __launch_bounds__(256, 2)
void gemm2_mma(const float* __restrict__ X, const float* __restrict__ b2,
               float* __restrict__ out) {
    __shared__ __align__(256) char smA[3][8192];
    __shared__ __align__(256) char smB[3][8192];

    const int tid = threadIdx.x;
    const int wid = tid >> 5, lane = tid & 31;
    const LdsmOff off = make_off(wid >> 2, wid & 3, lane);

    const int b = blockIdx.y;
    const int tc = (blockIdx.x >> 3) << 7;
    const int tp = (blockIdx.x & 7) << 7;
    const int e0 = g_expert[b][0], e1 = g_expert[b][1];
    const float s0 = g_scale[b][0], s1 = g_scale[b][1];

    const int ck = tid >> 4;
    const int cj = tid & 15;
    const uint32_t coff = (uint32_t)((ck << 8) + ((cj ^ (ck & 7)) << 4));
    const size_t tbA = (size_t)ck * CC + cj * 8;
    const size_t tbB = (size_t)ck * PP + cj * 8;
    const __nv_bfloat16* pA = &g_W2bf[e0][0][0] + tc + tbA;
    const __nv_bfloat16* pB = &g_Hbf[b][0][0][0] + tp + tbB;
    const __nv_bfloat16* A1 = &g_W2bf[e1][0][0] + tc + tbA;
    const __nv_bfloat16* H1 = &g_Hbf[b][1][0][0] + tp + tbB;

    uint32_t sa[3], sb[3];
#pragma unroll
    for (int i = 0; i < 3; i++) { sa[i] = smem_u32(smA[i]); sb[i] = smem_u32(smB[i]); }

    const int KT = 2 * DH / 32;   // 64
    cp_k32(sa[0], sb[0], coff, pA, CC, pB, PP); CP_COMMIT();
    pA += (size_t)32 * CC; pB += (size_t)32 * PP;
    cp_k32(sa[1], sb[1], coff, pA, CC, pB, PP); CP_COMMIT();
    pA += (size_t)32 * CC; pB += (size_t)32 * PP;

    float acc[4][4][4];
#pragma unroll
    for (int i = 0; i < 4; i++)
#pragma unroll
        for (int j = 0; j < 4; j++)
#pragma unroll
            for (int q = 0; q < 4; q++) acc[i][j][q] = 0.f;

    int st = 0, pf = 2;
#pragma unroll 1
    for (int kt = 0; kt < KT; kt++) {
        CP_WAIT1();
        __syncthreads();
        if (kt + 2 < KT) {
            if (kt + 2 == 32) { pA = A1; pB = H1; }   // slot switch
            cp_k32(sa[pf], sb[pf], coff, pA, CC, pB, PP);
            pA += (size_t)32 * CC; pB += (size_t)32 * PP;
        }
        CP_COMMIT();
        compute_k16(sa[st], sb[st], off, acc);
        compute_k16(sa[st] + 4096, sb[st] + 4096, off, acc);
        __syncthreads();
        if (++st == 3) st = 0;
        if (++pf == 3) pf = 0;
    }

    // epilogue: residual (fp32) + combined b2 bias inline
    const int warp_m = wid >> 2, warp_n = wid & 3;
    const int mrow = lane >> 2;
    const int ncol = (lane & 3) << 1;
#pragma unroll
    for (int mt = 0; mt < 4; mt++) {
#pragma unroll
        for (int h = 0; h < 2; h++) {
            int c = tc + warp_m * 64 + mt * 16 + mrow + h * 8;
            float cb = s0 * b2[e0 * CC + c] + s1 * b2[e1 * CC + c];
            size_t rowbase = ((size_t)(b * CC + c)) * PP + tp + warp_n * 32;
#pragma unroll
            for (int nt = 0; nt < 4; nt++) {
                float2 xin = *(const float2*)(X + rowbase + nt * 8 + ncol);
                float2 o;
                o.x = xin.x + cb + acc[mt][nt][h * 2 + 0];
                o.y = xin.y + cb + acc[mt][nt][h * 2 + 1];
                *(float2*)(out + rowbase + nt * 8 + ncol) = o;
            }
        }
    }
}

// ---------------------------------------------------------------------------
extern "C" void kernel_launch(void* const* d_in, const int* in_sizes, int n_in,
                              void* d_out, int out_size) {
    const float* inputs = (const float*)d_in[0];
    const float* kk     = (const float*)d_in[1];
    const float* Wg     = (const float*)d_in[2];
    const float* bg     = (const float*)d_in[3];
    const float* W1     = (const float*)d_in[4];
    const float* b1     = (const float*)d_in[5];
    const float* W2     = (const float*)d_in[6];
    const float* b2     = (const float*)d_in[7];
    float* out = (float*)d_out;

    __nv_bfloat16 *w1bf_p, *w2bf_p;
    cudaGetSymbolAddress((void**)&w1bf_p, g_W1bf);
    cudaGetSymbolAddress((void**)&w2bf_p, g_W2bf);

    const int n4 = EE * CC * DH / 4;
    f2bf_kernel<<<(2 * n4 + 255) / 256, 256>>>((const float4*)W1, (const float4*)W2,
                                               (uint2*)w1bf_p, (uint2*)w2bf_p, n4);
    mean_kernel<<<BB * CC, 256>>>(inputs);
    gate_kernel<<<1, 512>>>(Wg, bg, kk);
    gemm1_mma<<<dim3(64, 16), 256>>>(b1);
    gemm2_mma<<<dim3(32, 8), 256>>>(inputs, b2, out);
}

// round 8
// speedup vs baseline: 5.9316x; 1.0047x over previous
#include <cuda_runtime.h>
#include <cuda_bf16.h>
#include <math.h>
#include <stdint.h>

#define BB 8
#define CC 512
#define PP 1024   // H*W
#define EE 8
#define DH 1024

// Scratch (module-load allocation; none at runtime)
__device__ float g_mean[BB][CC];
__device__ float g_scale[BB][2];
__device__ int   g_expert[BB][2];
__device__ __nv_bfloat16 g_Xbf[BB][CC][PP];        // 8 MB
__device__ __nv_bfloat16 g_W1bf[EE][CC][DH];       // 8 MB
__device__ __nv_bfloat16 g_W2bf[EE][DH][CC];       // 8 MB
__device__ __nv_bfloat16 g_Hbf[BB][2][DH][PP];     // 32 MB

// ---------------------------------------------------------------------------
// helpers
// ---------------------------------------------------------------------------
__device__ __forceinline__ uint32_t smem_u32(const void* p) {
    uint32_t a;
    asm("{ .reg .u64 t; cvta.to.shared.u64 t, %1; cvt.u32.u64 %0, t; }" : "=r"(a) : "l"(p));
    return a;
}
__device__ __forceinline__ void mma_bf16(float* d, const uint32_t* a, const uint32_t* b) {
    asm volatile(
        "mma.sync.aligned.m16n8k16.row.col.f32.bf16.bf16.f32 "
        "{%0,%1,%2,%3}, {%4,%5,%6,%7}, {%8,%9}, {%0,%1,%2,%3};"
        : "+f"(d[0]), "+f"(d[1]), "+f"(d[2]), "+f"(d[3])
        : "r"(a[0]), "r"(a[1]), "r"(a[2]), "r"(a[3]), "r"(b[0]), "r"(b[1]));
}
#define LDSM_X4_T(r0, r1, r2, r3, addr) \
    asm volatile("ldmatrix.sync.aligned.m8n8.x4.trans.shared.b16 {%0,%1,%2,%3}, [%4];" \
        : "=r"(r0), "=r"(r1), "=r"(r2), "=r"(r3) : "r"(addr))
#define CP_ASYNC(dst, src) \
    asm volatile("cp.async.cg.shared.global [%0], [%1], 16;" :: "r"(dst), "l"(src))
#define CP_COMMIT() asm volatile("cp.async.commit_group;" ::: "memory")
#define CP_WAIT1()  asm volatile("cp.async.wait_group 1;" ::: "memory")

// Per-thread loop-invariant LDSM offsets (relative to k32-tile smem base).
// k32 tile = two 4KB k16 subtiles; subtile row = 256B = 16 chunks of 16B,
// chunk' = chunk ^ (k & 7)  — conflict-free for cp.async and ldmatrix.
struct LdsmOff { uint32_t a[4]; uint32_t b[2]; };
__device__ __forceinline__ LdsmOff make_off(int warp_m, int warp_n, int lane) {
    LdsmOff o;
    int kA = (lane & 7) | ((lane & 16) >> 1);
    int mh = (lane & 8) >> 3;
#pragma unroll
    for (int mt = 0; mt < 4; mt++) {
        int chunk = ((warp_m * 64 + mt * 16) >> 3) + mh;
        o.a[mt] = (uint32_t)((kA << 8) + ((chunk ^ (kA & 7)) << 4));
    }
    int kB = (lane & 7) | (lane & 8);
    int nh = (lane & 16) >> 1;
#pragma unroll
    for (int ntp = 0; ntp < 2; ntp++) {
        int chunk = (warp_n * 32 + ntp * 16 + nh) >> 3;
        o.b[ntp] = (uint32_t)((kB << 8) + ((chunk ^ (kB & 7)) << 4));
    }
    return o;
}

// one k16 subtile: 6 LDSM + 16 MMA, addresses = base + hoisted offset
__device__ __forceinline__ void compute_k16(uint32_t sA, uint32_t sB,
                                            const LdsmOff& o, float acc[4][4][4]) {
    uint32_t a[4][4];
#pragma unroll
    for (int mt = 0; mt < 4; mt++)
        LDSM_X4_T(a[mt][0], a[mt][1], a[mt][2], a[mt][3], sA + o.a[mt]);
    uint32_t bfr[2][4];
#pragma unroll
    for (int ntp = 0; ntp < 2; ntp++)
        LDSM_X4_T(bfr[ntp][0], bfr[ntp][1], bfr[ntp][2], bfr[ntp][3], sB + o.b[ntp]);
#pragma unroll
    for (int mt = 0; mt < 4; mt++)
#pragma unroll
        for (int nt = 0; nt < 4; nt++)
            mma_bf16(acc[mt][nt], a[mt], &bfr[nt >> 1][(nt & 1) << 1]);
}

// cp.async one k32 tile; pA/pB already carry the per-thread offset (k*ld + j*8)
__device__ __forceinline__ void cp_k32(uint32_t dstA, uint32_t dstB, uint32_t off,
                                       const __nv_bfloat16* pA, int ldA,
                                       const __nv_bfloat16* pB, int ldB) {
    CP_ASYNC(dstA + off, pA);
    CP_ASYNC(dstB + off, pB);
    CP_ASYNC(dstA + off + 4096, pA + (size_t)16 * ldA);
    CP_ASYNC(dstB + off + 4096, pB + (size_t)16 * ldB);
}

// ---------------------------------------------------------------------------
// Kernel 0: W1 + W2 f32 -> bf16 in one launch
// ---------------------------------------------------------------------------
__global__ void f2bf_kernel(const float4* __restrict__ in1, const float4* __restrict__ in2,
                            uint2* __restrict__ out1, uint2* __restrict__ out2, int n4) {
    int i = blockIdx.x * blockDim.x + threadIdx.x;
    const float4* src; uint2* dst; int idx;
    if (i < n4)      { src = in1; dst = out1; idx = i; }
    else             { src = in2; dst = out2; idx = i - n4; if (idx >= n4) return; }
    float4 v = src[idx];
    __nv_bfloat162 lo = __floats2bfloat162_rn(v.x, v.y);
    __nv_bfloat162 hi = __floats2bfloat162_rn(v.z, v.w);
    dst[idx] = make_uint2(*(uint32_t*)&lo, *(uint32_t*)&hi);
}

// ---------------------------------------------------------------------------
// Kernel 1: per-(b,c) spatial mean + X -> bf16 conversion (same read)
// ---------------------------------------------------------------------------
__global__ void mean_kernel(const float* __restrict__ x) {
    int bc = blockIdx.x;
    const float4* p = (const float4*)(x + (size_t)bc * PP);
    float4 v = p[threadIdx.x];
    __nv_bfloat162 lo = __floats2bfloat162_rn(v.x, v.y);
    __nv_bfloat162 hi = __floats2bfloat162_rn(v.z, v.w);
    uint2* xb = (uint2*)(&g_Xbf[0][0][0] + (size_t)bc * PP);
    xb[threadIdx.x] = make_uint2(*(uint32_t*)&lo, *(uint32_t*)&hi);

    float s = v.x + v.y + v.z + v.w;
#pragma unroll
    for (int o = 16; o; o >>= 1) s += __shfl_down_sync(0xffffffffu, s, o);
    __shared__ float ws[8];
    if ((threadIdx.x & 31) == 0) ws[threadIdx.x >> 5] = s;
    __syncthreads();
    if (threadIdx.x == 0) {
        float t = 0.f;
#pragma unroll
        for (int i = 0; i < 8; i++) t += ws[i];
        g_mean[bc >> 9][bc & 511] = t * (1.0f / PP);
    }
}

// ---------------------------------------------------------------------------
// Kernel 2: gate
// ---------------------------------------------------------------------------
__global__ void gate_kernel(const float* __restrict__ Wg, const float* __restrict__ bg,
                            const float* __restrict__ kk) {
    __shared__ float sl[BB][EE];
    int t = threadIdx.x;
    int w = t >> 5, lane = t & 31;
#pragma unroll
    for (int q = 0; q < 4; q++) {
        int pe = w * 4 + q;
        int b = pe >> 3, e = pe & 7;
        float acc = 0.f;
        for (int c = lane; c < CC; c += 32)
            acc = fmaf(g_mean[b][c], Wg[c * EE + e], acc);
#pragma unroll
        for (int o = 16; o; o >>= 1) acc += __shfl_down_sync(0xffffffffu, acc, o);
        if (lane == 0) sl[b][e] = acc + bg[e];
    }
    __syncthreads();
    if (t < BB) {
        int b = t;
        float m = -1e30f;
#pragma unroll
        for (int e = 0; e < EE; e++) m = fmaxf(m, sl[b][e]);
        float wv[EE]; float sum = 0.f;
#pragma unroll
        for (int e = 0; e < EE; e++) { wv[e] = expf(sl[b][e] - m); sum += wv[e]; }
        float inv = 1.0f / sum;
#pragma unroll
        for (int e = 0; e < EE; e++) wv[e] *= inv;
        int i0 = 0;
#pragma unroll
        for (int e = 1; e < EE; e++) if (wv[e] > wv[i0]) i0 = e;
        int i1 = (i0 == 0) ? 1 : 0;
#pragma unroll
        for (int e = 0; e < EE; e++) { if (e == i0 || e == i1) continue; if (wv[e] > wv[i1]) i1 = e; }
        float kb = kk[b];
        g_expert[b][0] = i0; g_expert[b][1] = i1;
        g_scale[b][0]  = wv[i0] * kb; g_scale[b][1] = wv[i1] * kb;
    }
}

// ---------------------------------------------------------------------------
// Kernel 3: GEMM1  H[d,p] = s * gelu(sum_c W1[e][c][d] X[b][c][p] + b1[e][d])
// ---------------------------------------------------------------------------
__global__ __launch_bounds__(256, 2)
void gemm1_mma(const float* __restrict__ b1v) {
    __shared__ __align__(256) char smA[3][8192];
    __shared__ __align__(256) char smB[3][8192];

    const int tid = threadIdx.x;
    const int wid = tid >> 5, lane = tid & 31;
    const LdsmOff off = make_off(wid >> 2, wid & 3, lane);

    const int pair = blockIdx.y;
    const int b = pair >> 1, slot = pair & 1;
    const int e = g_expert[b][slot];
    const float s = g_scale[b][slot];
    const int td = (blockIdx.x >> 3) << 7;
    const int tp = (blockIdx.x & 7) << 7;

    // per-thread cp.async source pointers / dst offset
    const int ck = tid >> 4;           // 0..15
    const int cj = tid & 15;           // 0..15
    const uint32_t coff = (uint32_t)((ck << 8) + ((cj ^ (ck & 7)) << 4));
    const __nv_bfloat16* pA = &g_W1bf[e][0][0] + td + (size_t)ck * DH + cj * 8;
    const __nv_bfloat16* pB = &g_Xbf[b][0][0] + tp + (size_t)ck * PP + cj * 8;

    uint32_t sa[3], sb[3];
#pragma unroll
    for (int i = 0; i < 3; i++) { sa[i] = smem_u32(smA[i]); sb[i] = smem_u32(smB[i]); }

    const int KT = CC / 32;   // 16
    cp_k32(sa[0], sb[0], coff, pA, DH, pB, PP); CP_COMMIT();
    pA += (size_t)32 * DH; pB += (size_t)32 * PP;
    cp_k32(sa[1], sb[1], coff, pA, DH, pB, PP); CP_COMMIT();
    pA += (size_t)32 * DH; pB += (size_t)32 * PP;

    float acc[4][4][4];
#pragma unroll
    for (int i = 0; i < 4; i++)
#pragma unroll
        for (int j = 0; j < 4; j++)
#pragma unroll
            for (int q = 0; q < 4; q++) acc[i][j][q] = 0.f;

    int st = 0, pf = 2;
#pragma unroll 1
    for (int kt = 0; kt < KT; kt++) {
        CP_WAIT1();
        __syncthreads();
        if (kt + 2 < KT) {
            cp_k32(sa[pf], sb[pf], coff, pA, DH, pB, PP);
            pA += (size_t)32 * DH; pB += (size_t)32 * PP;
        }
        CP_COMMIT();
        compute_k16(sa[st], sb[st], off, acc);
        compute_k16(sa[st] + 4096, sb[st] + 4096, off, acc);
        __syncthreads();
        if (++st == 3) st = 0;
        if (++pf == 3) pf = 0;
    }

    // epilogue: bias + exact gelu + scale -> g_Hbf (bf16)
    const int warp_m = wid >> 2, warp_n = wid & 3;
    const int mrow = lane >> 2;
    const int ncol = (lane & 3) << 1;
    __nv_bfloat16* Hbase = &g_Hbf[b][slot][0][0];
#pragma unroll
    for (int mt = 0; mt < 4; mt++) {
#pragma unroll
        for (int h = 0; h < 2; h++) {
            int d = td + warp_m * 64 + mt * 16 + mrow + h * 8;
            float bias = b1v[e * DH + d];
            __nv_bfloat16* Hrow = Hbase + (size_t)d * PP + tp + warp_n * 32;
#pragma unroll
            for (int nt = 0; nt < 4; nt++) {
                float x0 = acc[mt][nt][h * 2 + 0] + bias;
                float x1 = acc[mt][nt][h * 2 + 1] + bias;
                float o0 = s * (0.5f * x0 * (1.0f + erff(x0 * 0.70710678118654752f)));
                float o1 = s * (0.5f * x1 * (1.0f + erff(x1 * 0.70710678118654752f)));
                __nv_bfloat162 pk = __floats2bfloat162_rn(o0, o1);
                *(uint32_t*)(Hrow + nt * 8 + ncol) = *(uint32_t*)&pk;
            }
        }
    }
}

// ---------------------------------------------------------------------------
// Kernel 4: GEMM2  out = X + (s0 b2[e0] + s1 b2[e1]) + sum_slot W2[e]^T H
// ---------------------------------------------------------------------------
__global__ __launch_bounds__(256, 2)
void gemm2_mma(const float* __restrict__ X, const float* __restrict__ b2,
               float* __restrict__ out) {
    __shared__ __align__(256) char smA[3][8192];
    __shared__ __align__(256) char smB[3][8192];

    const int tid = threadIdx.x;
    const int wid = tid >> 5, lane = tid & 31;
    const LdsmOff off = make_off(wid >> 2, wid & 3, lane);

    const int b = blockIdx.y;
    const int tc = (blockIdx.x >> 3) << 7;
    const int tp = (blockIdx.x & 7) << 7;
    const int e0 = g_expert[b][0], e1 = g_expert[b][1];
    const float s0 = g_scale[b][0], s1 = g_scale[b][1];

    const int ck = tid >> 4;
    const int cj = tid & 15;
    const uint32_t coff = (uint32_t)((ck << 8) + ((cj ^ (ck & 7)) << 4));
    const size_t tbA = (size_t)ck * CC + cj * 8;
    const size_t tbB = (size_t)ck * PP + cj * 8;
    const __nv_bfloat16* pA = &g_W2bf[e0][0][0] + tc + tbA;
    const __nv_bfloat16* pB = &g_Hbf[b][0][0][0] + tp + tbB;
    const __nv_bfloat16* A1 = &g_W2bf[e1][0][0] + tc + tbA;
    const __nv_bfloat16* H1 = &g_Hbf[b][1][0][0] + tp + tbB;

    uint32_t sa[3], sb[3];
#pragma unroll
    for (int i = 0; i < 3; i++) { sa[i] = smem_u32(smA[i]); sb[i] = smem_u32(smB[i]); }

    const int KT = 2 * DH / 32;   // 64
    cp_k32(sa[0], sb[0], coff, pA, CC, pB, PP); CP_COMMIT();
    pA += (size_t)32 * CC; pB += (size_t)32 * PP;
    cp_k32(sa[1], sb[1], coff, pA, CC, pB, PP); CP_COMMIT();
    pA += (size_t)32 * CC; pB += (size_t)32 * PP;

    float acc[4][4][4];
#pragma unroll
    for (int i = 0; i < 4; i++)
#pragma unroll
        for (int j = 0; j < 4; j++)
#pragma unroll
            for (int q = 0; q < 4; q++) acc[i][j][q] = 0.f;

    int st = 0, pf = 2;
#pragma unroll 1
    for (int kt = 0; kt < KT; kt++) {
        CP_WAIT1();
        __syncthreads();
        if (kt + 2 < KT) {
            if (kt + 2 == 32) { pA = A1; pB = H1; }   // slot switch
            cp_k32(sa[pf], sb[pf], coff, pA, CC, pB, PP);
            pA += (size_t)32 * CC; pB += (size_t)32 * PP;
        }
        CP_COMMIT();
        compute_k16(sa[st], sb[st], off, acc);
        compute_k16(sa[st] + 4096, sb[st] + 4096, off, acc);
        __syncthreads();
        if (++st == 3) st = 0;
        if (++pf == 3) pf = 0;
    }

    // epilogue: residual (fp32) + combined b2 bias inline
    const int warp_m = wid >> 2, warp_n = wid & 3;
    const int mrow = lane >> 2;
    const int ncol = (lane & 3) << 1;
#pragma unroll
    for (int mt = 0; mt < 4; mt++) {
#pragma unroll
        for (int h = 0; h < 2; h++) {
            int c = tc + warp_m * 64 + mt * 16 + mrow + h * 8;
            float cb = s0 * b2[e0 * CC + c] + s1 * b2[e1 * CC + c];
            size_t rowbase = ((size_t)(b * CC + c)) * PP + tp + warp_n * 32;
#pragma unroll
            for (int nt = 0; nt < 4; nt++) {
                float2 xin = *(const float2*)(X + rowbase + nt * 8 + ncol);
                float2 o;
                o.x = xin.x + cb + acc[mt][nt][h * 2 + 0];
                o.y = xin.y + cb + acc[mt][nt][h * 2 + 1];
                *(float2*)(out + rowbase + nt * 8 + ncol) = o;
            }
        }
    }
}

// ---------------------------------------------------------------------------
extern "C" void kernel_launch(void* const* d_in, const int* in_sizes, int n_in,
                              void* d_out, int out_size) {
    const float* inputs = (const float*)d_in[0];
    const float* kk     = (const float*)d_in[1];
    const float* Wg     = (const float*)d_in[2];
    const float* bg     = (const float*)d_in[3];
    const float* W1     = (const float*)d_in[4];
    const float* b1     = (const float*)d_in[5];
    const float* W2     = (const float*)d_in[6];
    const float* b2     = (const float*)d_in[7];
    float* out = (float*)d_out;

    __nv_bfloat16 *w1bf_p, *w2bf_p;
    cudaGetSymbolAddress((void**)&w1bf_p, g_W1bf);
    cudaGetSymbolAddress((void**)&w2bf_p, g_W2bf);

    const int n4 = EE * CC * DH / 4;
    f2bf_kernel<<<(2 * n4 + 255) / 256, 256>>>((const float4*)W1, (const float4*)W2,
                                               (uint2*)w1bf_p, (uint2*)w2bf_p, n4);
    mean_kernel<<<BB * CC, 256>>>(inputs);
    gate_kernel<<<1, 512>>>(Wg, bg, kk);
    gemm1_mma<<<dim3(64, 16), 256>>>(b1);
    gemm2_mma<<<dim3(32, 8), 256>>>(inputs, b2, out);
}